// round 1
// baseline (speedup 1.0000x reference)
#include <cuda_runtime.h>
#include <cuda_bf16.h>
#include <math.h>

#define NB      4
#define LEN     5440
#define MTOT    (NB*LEN)      // 21760
#define DM      256
#define NH      8
#define NL      4
#define NP      4
#define DH      32
#define NG      128           // NH*NL*NP
#define OFFD    32

// scratch (static device globals; allocation-free)
__device__ float g_value[MTOT*DM];     // value projection  (b,lin,h,d) linear
__device__ float g_mix[MTOT*DM];       // pre-output-proj   (b,q,h,d)  linear
__device__ float g_offaw[MTOT*NG*3];   // per (b,q,group): ox_raw, oy_raw, logit_raw

// ---------------------------------------------------------------------------
// Shared-structure GEMM: C[M x 256] = A[M x 256] @ W[256 x 256]^T + bias
// Block: 128 rows of A resident in smem (k-major, swizzled). grid (170, 4),
// each block does 2 chunks of 32 output columns.
// ---------------------------------------------------------------------------
extern "C" __global__ void __launch_bounds__(256, 1)
gemm256(const float* __restrict__ A, const float* __restrict__ W,
        const float* __restrict__ bias, float* __restrict__ C) {
  extern __shared__ float sm[];
  float* qs = sm;              // [256][128] k-major, swizzled
  float* ws = sm + 256*128;    // [256][32]  k-major, swizzled
  const int tid = threadIdx.x;
  const int r0 = blockIdx.x * 128;

  // load & transpose A tile into qs[k][m]
#pragma unroll
  for (int i = 0; i < 32; ++i) {
    int f  = i*256 + tid;
    int m  = f >> 6;           // 0..127
    int kc = f & 63;           // float4 index along k
    float4 v = reinterpret_cast<const float4*>(A)[(size_t)(r0+m)*64 + kc];
    int k0 = kc*4;
    int q  = m ^ ((kc & 7)*4); // bank swizzle
    qs[(k0+0)*128 + q] = v.x;
    qs[(k0+1)*128 + q] = v.y;
    qs[(k0+2)*128 + q] = v.z;
    qs[(k0+3)*128 + q] = v.w;
  }

  const int qi = tid >> 3, di = tid & 7;
  const int q0 = qi*4,  d0 = di*4;

  for (int ci = 0; ci < 2; ++ci) {
    int chunk = blockIdx.y*2 + ci;
    __syncthreads();
    // load W chunk rows [chunk*32, chunk*32+32) transposed into ws[k][d]
#pragma unroll
    for (int i = 0; i < 8; ++i) {
      int f  = i*256 + tid;
      int d  = f >> 6;
      int kc = f & 63;
      float4 v = reinterpret_cast<const float4*>(W)[(size_t)(chunk*32 + d)*64 + kc];
      int k0 = kc*4;
      int dd = d ^ ((kc & 7)*4);
      ws[(k0+0)*32 + dd] = v.x;
      ws[(k0+1)*32 + dd] = v.y;
      ws[(k0+2)*32 + dd] = v.z;
      ws[(k0+3)*32 + dd] = v.w;
    }
    __syncthreads();

    float acc[4][4];
#pragma unroll
    for (int a = 0; a < 4; ++a)
#pragma unroll
      for (int b = 0; b < 4; ++b) acc[a][b] = 0.f;

#pragma unroll 8
    for (int k = 0; k < 256; ++k) {
      int sw = ((k >> 2) & 7) * 4;
      float4 av = *reinterpret_cast<const float4*>(&qs[k*128 + (q0 ^ sw)]);
      float4 bv = *reinterpret_cast<const float4*>(&ws[k*32  + (d0 ^ sw)]);
      float aa[4] = {av.x, av.y, av.z, av.w};
      float bb[4] = {bv.x, bv.y, bv.z, bv.w};
#pragma unroll
      for (int x = 0; x < 4; ++x)
#pragma unroll
        for (int y = 0; y < 4; ++y) acc[x][y] += aa[x]*bb[y];
    }

    int n0 = chunk*32 + d0;
    float4 bs = *reinterpret_cast<const float4*>(bias + n0);
#pragma unroll
    for (int qq = 0; qq < 4; ++qq) {
      float4 o;
      o.x = acc[qq][0] + bs.x;
      o.y = acc[qq][1] + bs.y;
      o.z = acc[qq][2] + bs.z;
      o.w = acc[qq][3] + bs.w;
      reinterpret_cast<float4*>(C)[(size_t)(r0+q0+qq)*64 + (n0 >> 2)] = o;
    }
  }
}

__device__ __forceinline__ float silu_f(float x) {
  return x / (1.f + __expf(-x));
}

// ---------------------------------------------------------------------------
// Fused offset-embed GEMM + silu + (h,l,k)-group reduction.
// oe[g*32+d] = silu(q . Wemb[g*32+d, :]);  per group g:
//   ox = sum_d oe*sow[g,d,0], oy = sum_d oe*sow[g,d,1], logit = sum_d oe*attw[g,d]
// grid (170, 4): block handles 128 queries x 32 groups.
// ---------------------------------------------------------------------------
extern "C" __global__ void __launch_bounds__(256, 1)
offset_kernel(const float* __restrict__ Q, const float* __restrict__ Wemb,
              const float* __restrict__ sow, const float* __restrict__ attw) {
  extern __shared__ float sm[];
  float* qs = sm;              // [256][128]
  float* ws = sm + 256*128;    // [256][32]
  const int tid = threadIdx.x;
  const int r0 = blockIdx.x * 128;

#pragma unroll
  for (int i = 0; i < 32; ++i) {
    int f  = i*256 + tid;
    int m  = f >> 6;
    int kc = f & 63;
    float4 v = reinterpret_cast<const float4*>(Q)[(size_t)(r0+m)*64 + kc];
    int k0 = kc*4;
    int q  = m ^ ((kc & 7)*4);
    qs[(k0+0)*128 + q] = v.x;
    qs[(k0+1)*128 + q] = v.y;
    qs[(k0+2)*128 + q] = v.z;
    qs[(k0+3)*128 + q] = v.w;
  }

  const int qi = tid >> 3, di = tid & 7;
  const int q0 = qi*4,  d0 = di*4;
  const float4* sow4  = reinterpret_cast<const float4*>(sow);
  const float4* attw4 = reinterpret_cast<const float4*>(attw);

  for (int gi = 0; gi < 32; ++gi) {
    int g = blockIdx.y*32 + gi;
    __syncthreads();
#pragma unroll
    for (int i = 0; i < 8; ++i) {
      int f  = i*256 + tid;
      int d  = f >> 6;
      int kc = f & 63;
      float4 v = reinterpret_cast<const float4*>(Wemb)[(size_t)(g*32 + d)*64 + kc];
      int k0 = kc*4;
      int dd = d ^ ((kc & 7)*4);
      ws[(k0+0)*32 + dd] = v.x;
      ws[(k0+1)*32 + dd] = v.y;
      ws[(k0+2)*32 + dd] = v.z;
      ws[(k0+3)*32 + dd] = v.w;
    }
    __syncthreads();

    float acc[4][4];
#pragma unroll
    for (int a = 0; a < 4; ++a)
#pragma unroll
      for (int b = 0; b < 4; ++b) acc[a][b] = 0.f;

#pragma unroll 8
    for (int k = 0; k < 256; ++k) {
      int sw = ((k >> 2) & 7) * 4;
      float4 av = *reinterpret_cast<const float4*>(&qs[k*128 + (q0 ^ sw)]);
      float4 bv = *reinterpret_cast<const float4*>(&ws[k*32  + (d0 ^ sw)]);
      float aa[4] = {av.x, av.y, av.z, av.w};
      float bb[4] = {bv.x, bv.y, bv.z, bv.w};
#pragma unroll
      for (int x = 0; x < 4; ++x)
#pragma unroll
        for (int y = 0; y < 4; ++y) acc[x][y] += aa[x]*bb[y];
    }

    // epilogue: silu + reduce over the 32-dim offset axis (8 lanes x 4 each)
    int base = g*32 + d0;
    float4 s0 = sow4[(base >> 1)    ];   // {d0.x, d0.y, d1.x, d1.y}
    float4 s1 = sow4[(base >> 1) + 1];   // {d2.x, d2.y, d3.x, d3.y}
    float4 wv = attw4[base >> 2];        // {d0..d3}
#pragma unroll
    for (int qq = 0; qq < 4; ++qq) {
      float v0 = silu_f(acc[qq][0]);
      float v1 = silu_f(acc[qq][1]);
      float v2 = silu_f(acc[qq][2]);
      float v3 = silu_f(acc[qq][3]);
      float sx = v0*s0.x + v1*s0.z + v2*s1.x + v3*s1.z;
      float sy = v0*s0.y + v1*s0.w + v2*s1.y + v3*s1.w;
      float sl = v0*wv.x + v1*wv.y + v2*wv.z + v3*wv.w;
#pragma unroll
      for (int off = 4; off; off >>= 1) {
        sx += __shfl_down_sync(0xffffffffu, sx, off, 8);
        sy += __shfl_down_sync(0xffffffffu, sy, off, 8);
        sl += __shfl_down_sync(0xffffffffu, sl, off, 8);
      }
      if (di == 0) {
        size_t o = (size_t)(r0 + q0 + qq)*(NG*3) + (size_t)g*3;
        g_offaw[o+0] = sx;
        g_offaw[o+1] = sy;
        g_offaw[o+2] = sl;
      }
    }
  }
}

// ---------------------------------------------------------------------------
// Sampling: one warp per (b,q,head). Lane = d_head dim (coalesced gathers).
// ---------------------------------------------------------------------------
extern "C" __global__ void __launch_bounds__(256)
sample_kernel(const float* __restrict__ ref, const float* __restrict__ sob,
              const float* __restrict__ attb) {
  __shared__ float s_lx[NH][16], s_ly[NH][16], s_aw[NH][16];
  const int bq   = blockIdx.x;
  const int b    = bq / LEN;
  const int h    = threadIdx.x >> 5;
  const int lane = threadIdx.x & 31;
  const int p    = lane & 15;       // point index (lanes 16..31 duplicate)
  const int l    = p >> 2;
  const int kpt  = p & 3;

  const float SZ[4] = {64.f, 32.f, 16.f, 8.f};

  size_t ob = (size_t)bq*(NG*3) + (size_t)(h*16 + p)*3;
  float rx = g_offaw[ob+0], ry = g_offaw[ob+1], rl = g_offaw[ob+2];
  int hlk = (h*NL + l)*NP + kpt;
  float inv = 1.f / SZ[l];
  float lx = ref[(size_t)bq*8 + l*2 + 0] + (rx + sob[hlk*2+0]) * inv;
  float ly = ref[(size_t)bq*8 + l*2 + 1] + (ry + sob[hlk*2+1]) * inv;
  float logit = rl + attb[hlk];

  // softmax over 16 points (width-16 segments; both halves identical)
  float mx = logit;
#pragma unroll
  for (int off = 8; off; off >>= 1)
    mx = fmaxf(mx, __shfl_xor_sync(0xffffffffu, mx, off, 16));
  float e = __expf(logit - mx);
  float ssum = e;
#pragma unroll
  for (int off = 8; off; off >>= 1)
    ssum += __shfl_xor_sync(0xffffffffu, ssum, off, 16);
  float aw = e / ssum;

  if (lane < 16) { s_lx[h][p] = lx; s_ly[h][p] = ly; s_aw[h][p] = aw; }
  __syncwarp(0xffffffffu);

  const int ST[4]  = {0, 4096, 5120, 5376};
  const int SZI[4] = {64, 32, 16, 8};
  float acc = 0.f;
  const float* vbase = g_value + (size_t)b*LEN*DM + h*DH + lane;

#pragma unroll
  for (int pp = 0; pp < 16; ++pp) {
    int ll = pp >> 2;
    int S  = SZI[ll];
    float x = s_lx[h][pp]*(float)S - 0.5f;
    float y = s_ly[h][pp]*(float)S - 0.5f;
    float w = s_aw[h][pp];
    float fx = floorf(x), fy = floorf(y);
    int x0 = (int)fx, y0 = (int)fy;
    float wx = x - fx, wy = y - fy;
    const float* vl = vbase + (size_t)ST[ll]*DM;
    float v00 = 0.f, v01 = 0.f, v10 = 0.f, v11 = 0.f;
    bool xa = (x0   >= 0) && (x0   < S);
    bool xb = (x0+1 >= 0) && (x0+1 < S);
    bool ya = (y0   >= 0) && (y0   < S);
    bool yb = (y0+1 >= 0) && (y0+1 < S);
    if (xa && ya) v00 = vl[(size_t)(y0*S + x0  )*DM];
    if (xb && ya) v01 = vl[(size_t)(y0*S + x0+1)*DM];
    if (xa && yb) v10 = vl[(size_t)((y0+1)*S + x0  )*DM];
    if (xb && yb) v11 = vl[(size_t)((y0+1)*S + x0+1)*DM];
    acc += w * ((v00*(1.f-wx) + v01*wx)*(1.f-wy) + (v10*(1.f-wx) + v11*wx)*wy);
  }
  g_mix[(size_t)bq*DM + h*DH + lane] = acc;
}

// ---------------------------------------------------------------------------
extern "C" void kernel_launch(void* const* d_in, const int* in_sizes, int n_in,
                              void* d_out, int out_size) {
  (void)in_sizes; (void)n_in; (void)out_size;
  const float* query  = (const float*)d_in[0];
  const float* ref    = (const float*)d_in[1];
  const float* inputf = (const float*)d_in[2];
  // d_in[3] = input_spatial_shapes (static pyramid; hardcoded)
  const float* oeW    = (const float*)d_in[4];
  const float* sow    = (const float*)d_in[5];
  const float* sob    = (const float*)d_in[6];
  const float* attW   = (const float*)d_in[7];
  const float* attb   = (const float*)d_in[8];
  const float* valW   = (const float*)d_in[9];
  const float* valb   = (const float*)d_in[10];
  const float* outW   = (const float*)d_in[11];
  const float* outb   = (const float*)d_in[12];
  float* out = (float*)d_out;

  float *pval, *pmix;
  cudaGetSymbolAddress((void**)&pval, g_value);
  cudaGetSymbolAddress((void**)&pmix, g_mix);

  const size_t smem = (size_t)(256*128 + 256*32) * sizeof(float); // 160 KB
  cudaFuncSetAttribute(gemm256, cudaFuncAttributeMaxDynamicSharedMemorySize, (int)smem);
  cudaFuncSetAttribute(offset_kernel, cudaFuncAttributeMaxDynamicSharedMemorySize, (int)smem);

  dim3 gg(MTOT/128, 4);
  gemm256<<<gg, 256, smem>>>(inputf, valW, valb, pval);      // value projection
  offset_kernel<<<gg, 256, smem>>>(query, oeW, sow, attW);   // offsets + logits
  sample_kernel<<<MTOT, 256>>>(ref, sob, attb);              // bilinear + softmax mix
  gemm256<<<gg, 256, smem>>>(pmix, outW, outb, out);         // output projection
}

// round 5
// speedup vs baseline: 2.4543x; 2.4543x over previous
#include <cuda_runtime.h>
#include <cuda_bf16.h>
#include <math.h>
#include <stdint.h>

#define NB   4
#define LEN  5440
#define MTOT (NB*LEN)      // 21760
#define DM   256
#define NH   8
#define NG   128

// ===========================================================================
// Scratch (allocation-free __device__ globals)
// ===========================================================================
__device__ uint4 g_qh[MTOT*32],  g_ql[MTOT*32];      // query split (row-major bf16)
__device__ uint4 g_ifh[MTOT*32], g_ifl[MTOT*32];     // input_flatten split
__device__ uint4 g_mh[MTOT*32],  g_ml[MTOT*32];      // mix (sample output) split
__device__ uint4 g_wembh[4096*32], g_wembl[4096*32]; // offset-embed W split
__device__ uint4 g_vwh[256*32],   g_vwl[256*32];     // value W split
__device__ uint4 g_owh[256*32],   g_owl[256*32];     // out W split
__device__ float g_value[MTOT*DM];
__device__ float g_offaw[(size_t)NG*MTOT*3];         // [group][row][3]

// ===========================================================================
__device__ __forceinline__ uint32_t s2u(const void* p) {
  uint32_t a;
  asm("{ .reg .u64 t; cvta.to.shared.u64 t, %1; cvt.u32.u64 %0, t; }" : "=r"(a) : "l"(p));
  return a;
}
__device__ __forceinline__ void ldsm4(uint32_t& r0, uint32_t& r1, uint32_t& r2,
                                      uint32_t& r3, uint32_t addr) {
  asm volatile("ldmatrix.sync.aligned.m8n8.x4.shared.b16 {%0,%1,%2,%3}, [%4];"
               : "=r"(r0), "=r"(r1), "=r"(r2), "=r"(r3) : "r"(addr));
}
__device__ __forceinline__ void mma16816(float& c0, float& c1, float& c2, float& c3,
                                         uint32_t a0, uint32_t a1, uint32_t a2, uint32_t a3,
                                         uint32_t b0, uint32_t b1) {
  asm volatile("mma.sync.aligned.m16n8k16.row.col.f32.bf16.bf16.f32 "
               "{%0,%1,%2,%3}, {%4,%5,%6,%7}, {%8,%9}, {%0,%1,%2,%3};"
               : "+f"(c0), "+f"(c1), "+f"(c2), "+f"(c3)
               : "r"(a0), "r"(a1), "r"(a2), "r"(a3), "r"(b0), "r"(b1));
}
#define CP_ASYNC16(dst, src) \
  asm volatile("cp.async.cg.shared.global [%0], [%1], 16;" :: "r"(dst), "l"(src))
#define CP_COMMIT() asm volatile("cp.async.commit_group;")
#define CP_WAIT(n)  asm volatile("cp.async.wait_group %0;" :: "n"(n) : "memory")

// ===========================================================================
// prep: split fp32 row-major -> bf16 hi/lo row-major
// ===========================================================================
__global__ void __launch_bounds__(256)
split_rm(const float4* __restrict__ in, __nv_bfloat162* __restrict__ hi,
         __nv_bfloat162* __restrict__ lo, int n4) {
  int i = blockIdx.x*256 + threadIdx.x;
  if (i >= n4) return;
  float4 v = in[i];
  __nv_bfloat16 hx = __float2bfloat16_rn(v.x);
  __nv_bfloat16 hy = __float2bfloat16_rn(v.y);
  __nv_bfloat16 hz = __float2bfloat16_rn(v.z);
  __nv_bfloat16 hw = __float2bfloat16_rn(v.w);
  hi[2*i+0] = __nv_bfloat162(hx, hy);
  hi[2*i+1] = __nv_bfloat162(hz, hw);
  lo[2*i+0] = __nv_bfloat162(__float2bfloat16_rn(v.x - __bfloat162float(hx)),
                             __float2bfloat16_rn(v.y - __bfloat162float(hy)));
  lo[2*i+1] = __nv_bfloat162(__float2bfloat16_rn(v.z - __bfloat162float(hz)),
                             __float2bfloat16_rn(v.w - __bfloat162float(hw)));
}

// ===========================================================================
// Split-bf16 warp-MMA GEMM. C[Mx(NT*128)] = A @ B^T (3-term split, eff K=768).
// Block: 128 rows x 128 cols, 8 warps (4M x 2N), A hi|lo resident in smem.
// MODE 0: bias + fp32 store.  MODE 1: silu + group-of-32 dot -> g_offaw.
// ===========================================================================
template<int MODE, int NT>
__global__ void __launch_bounds__(256, 1)
gemm_mma(const uint4* __restrict__ Ah, const uint4* __restrict__ Al,
         const uint4* __restrict__ Bh, const uint4* __restrict__ Bl,
         const float* __restrict__ c0, const float* __restrict__ c1,
         float* __restrict__ Out) {
  extern __shared__ char dsm[];
  const uint32_t as = s2u(dsm);            // A: 128 rows x 1024B = 131072
  const uint32_t bsb = as + 131072u;       // B: 2 x 32768
  const int tid = threadIdx.x;
  const int wid = tid >> 5, lane = tid & 31;
  const int mw = wid & 3, nw = wid >> 2;
  const int r0 = blockIdx.x * 128;
  const int N0 = blockIdx.y * NT * 128;

  // ---- load A (hi segs 0-3, lo segs 4-7 per 1KB row), swizzled ----
#pragma unroll
  for (int it = 0; it < 32; ++it) {
    int i = it*256 + tid;                  // 0..8191
    int r = i >> 6, u = i & 63;
    int half = u >> 5, uu = u & 31;
    int s = (half << 2) + (uu >> 3), c = uu & 7;
    const uint4* src = (half ? Al : Ah) + (size_t)(r0 + r)*32 + uu;
    uint32_t dst = as + (uint32_t)r*1024u + (uint32_t)s*128u + (uint32_t)((c ^ (r & 7))*16);
    CP_ASYNC16(dst, src);
  }
  CP_COMMIT();

  // lane-invariant pieces
  const int lA = mw*32 + (lane & 15);      // A row within tile
  const int jj = lane >> 4;                // 8-col group
  const int nB = nw*64 + (lane & 15);      // B row within tile
  const uint32_t pA = as + (uint32_t)lA*1024u;
  const int swA = lA & 7, swB = nB & 7;

  for (int nt = 0; nt < NT; ++nt) {
    float acc[2][8][4];
#pragma unroll
    for (int a = 0; a < 2; ++a)
#pragma unroll
      for (int b = 0; b < 8; ++b)
#pragma unroll
        for (int d = 0; d < 4; ++d) acc[a][b][d] = 0.f;

    const int nrow0 = N0 + nt*128;
    // prefetch super-chunk 0
    {
#pragma unroll
      for (int it = 0; it < 8; ++it) {
        int i = it*256 + tid;              // 0..2047
        int n = i >> 4, u = i & 15;
        int sub = u >> 3, c = u & 7;
        int chunk = sub;                   // sc=0
        int term = chunk >> 2, c4 = chunk & 3;
        const uint4* src = ((term == 1) ? Bl : Bh) + (size_t)(nrow0 + n)*32 + c4*8 + c;
        uint32_t dst = bsb + (uint32_t)sub*16384u + (uint32_t)n*128u + (uint32_t)((c ^ (n & 7))*16);
        CP_ASYNC16(dst, src);
      }
      CP_COMMIT();
    }

    for (int sc = 0; sc < 6; ++sc) {
      if (sc + 1 < 6) {
#pragma unroll
        for (int it = 0; it < 8; ++it) {
          int i = it*256 + tid;
          int n = i >> 4, u = i & 15;
          int sub = u >> 3, c = u & 7;
          int chunk = (sc + 1)*2 + sub;
          int term = chunk >> 2, c4 = chunk & 3;
          const uint4* src = ((term == 1) ? Bl : Bh) + (size_t)(nrow0 + n)*32 + c4*8 + c;
          uint32_t dst = bsb + (uint32_t)((sc + 1) & 1)*32768u + (uint32_t)sub*16384u
                       + (uint32_t)n*128u + (uint32_t)((c ^ (n & 7))*16);
          CP_ASYNC16(dst, src);
        }
        CP_COMMIT();
        CP_WAIT(1);
      } else {
        CP_WAIT(0);
      }
      __syncthreads();

      const uint32_t bs = bsb + (uint32_t)(sc & 1)*32768u;
#pragma unroll
      for (int sub = 0; sub < 2; ++sub) {
        const int chunk = sc*2 + sub;
        const int term = chunk >> 2, c4 = chunk & 3;
        const int aseg = ((term == 2) ? 4 : 0) + c4;
        const uint32_t aB = pA + (uint32_t)aseg*128u;
        const uint32_t bB = bs + (uint32_t)sub*16384u + (uint32_t)nB*128u;
#pragma unroll
        for (int ks = 0; ks < 4; ++ks) {
          const int cc = ks*2 + jj;
          uint32_t a0[4], a1[4];
          ldsm4(a0[0], a0[1], a0[2], a0[3], aB + (uint32_t)((cc ^ swA)*16));
          ldsm4(a1[0], a1[1], a1[2], a1[3], aB + 16384u + (uint32_t)((cc ^ swA)*16));
          uint32_t bq[4][4];
#pragma unroll
          for (int qt = 0; qt < 4; ++qt)
            ldsm4(bq[qt][0], bq[qt][1], bq[qt][2], bq[qt][3],
                  bB + (uint32_t)qt*2048u + (uint32_t)((cc ^ swB)*16));
#pragma unroll
          for (int qt = 0; qt < 4; ++qt) {
            mma16816(acc[0][qt*2  ][0], acc[0][qt*2  ][1], acc[0][qt*2  ][2], acc[0][qt*2  ][3],
                     a0[0], a0[1], a0[2], a0[3], bq[qt][0], bq[qt][2]);
            mma16816(acc[0][qt*2+1][0], acc[0][qt*2+1][1], acc[0][qt*2+1][2], acc[0][qt*2+1][3],
                     a0[0], a0[1], a0[2], a0[3], bq[qt][1], bq[qt][3]);
            mma16816(acc[1][qt*2  ][0], acc[1][qt*2  ][1], acc[1][qt*2  ][2], acc[1][qt*2  ][3],
                     a1[0], a1[1], a1[2], a1[3], bq[qt][0], bq[qt][2]);
            mma16816(acc[1][qt*2+1][0], acc[1][qt*2+1][1], acc[1][qt*2+1][2], acc[1][qt*2+1][3],
                     a1[0], a1[1], a1[2], a1[3], bq[qt][1], bq[qt][3]);
          }
        }
      }
      __syncthreads();
    }

    // ---- epilogue ----
    if (MODE == 0) {
#pragma unroll
      for (int mt = 0; mt < 2; ++mt)
#pragma unroll
        for (int h = 0; h < 2; ++h) {
          int row = r0 + mw*32 + mt*16 + (lane >> 2) + h*8;
#pragma unroll
          for (int j = 0; j < 8; ++j) {
            int col = nt*128 + nw*64 + j*8 + (lane & 3)*2;
            float2 o;
            o.x = acc[mt][j][h*2+0] + c0[col];
            o.y = acc[mt][j][h*2+1] + c0[col+1];
            *reinterpret_cast<float2*>(Out + (size_t)row*256 + col) = o;
          }
        }
    } else {
      const float2* sw2 = reinterpret_cast<const float2*>(c0);
#pragma unroll
      for (int grp = 0; grp < 2; ++grp) {
        int g = (N0 + nt*128 + nw*64 + grp*32) >> 5;
        float wx[4][2], wy[4][2], wl[4][2];
#pragma unroll
        for (int j = 0; j < 4; ++j) {
          int col = g*32 + j*8 + (lane & 3)*2;
          float2 q0 = __ldg(&sw2[col]), q1 = __ldg(&sw2[col+1]);
          wx[j][0] = q0.x; wy[j][0] = q0.y;
          wx[j][1] = q1.x; wy[j][1] = q1.y;
          wl[j][0] = __ldg(&c1[col]); wl[j][1] = __ldg(&c1[col+1]);
        }
#pragma unroll
        for (int mt = 0; mt < 2; ++mt)
#pragma unroll
          for (int h = 0; h < 2; ++h) {
            int row = r0 + mw*32 + mt*16 + (lane >> 2) + h*8;
            float sx = 0.f, sy = 0.f, sl = 0.f;
#pragma unroll
            for (int j = 0; j < 4; ++j) {
              float v0 = acc[mt][grp*4+j][h*2+0];
              float v1 = acc[mt][grp*4+j][h*2+1];
              v0 = v0 / (1.f + __expf(-v0));
              v1 = v1 / (1.f + __expf(-v1));
              sx = fmaf(v0, wx[j][0], sx); sx = fmaf(v1, wx[j][1], sx);
              sy = fmaf(v0, wy[j][0], sy); sy = fmaf(v1, wy[j][1], sy);
              sl = fmaf(v0, wl[j][0], sl); sl = fmaf(v1, wl[j][1], sl);
            }
            sx += __shfl_xor_sync(0xffffffffu, sx, 1);
            sy += __shfl_xor_sync(0xffffffffu, sy, 1);
            sl += __shfl_xor_sync(0xffffffffu, sl, 1);
            sx += __shfl_xor_sync(0xffffffffu, sx, 2);
            sy += __shfl_xor_sync(0xffffffffu, sy, 2);
            sl += __shfl_xor_sync(0xffffffffu, sl, 2);
            if ((lane & 3) == 0) {
              float* o = Out + ((size_t)g*MTOT + row)*3;
              o[0] = sx; o[1] = sy; o[2] = sl;
            }
          }
      }
    }
  }
}

// ===========================================================================
// Sampling: one warp per (b,q,head). Writes mix as split bf16 for out-proj.
// ===========================================================================
__global__ void __launch_bounds__(256)
sample_kernel(const float* __restrict__ ref, const float* __restrict__ sob,
              const float* __restrict__ attb) {
  __shared__ float s_lx[NH][16], s_ly[NH][16], s_aw[NH][16];
  const int bq   = blockIdx.x;
  const int b    = bq / LEN;
  const int h    = threadIdx.x >> 5;
  const int lane = threadIdx.x & 31;
  const int p    = lane & 15;
  const int l    = p >> 2;

  const float SZ[4] = {64.f, 32.f, 16.f, 8.f};
  int g = h*16 + p;
  size_t ob = ((size_t)g*MTOT + bq)*3;
  float rx = g_offaw[ob+0], ry = g_offaw[ob+1], rl = g_offaw[ob+2];
  float inv = 1.f / SZ[l];
  float lx = ref[(size_t)bq*8 + l*2 + 0] + (rx + sob[g*2+0]) * inv;
  float ly = ref[(size_t)bq*8 + l*2 + 1] + (ry + sob[g*2+1]) * inv;
  float logit = rl + attb[g];

  float mx = logit;
#pragma unroll
  for (int off = 8; off; off >>= 1)
    mx = fmaxf(mx, __shfl_xor_sync(0xffffffffu, mx, off, 16));
  float e = __expf(logit - mx);
  float ssum = e;
#pragma unroll
  for (int off = 8; off; off >>= 1)
    ssum += __shfl_xor_sync(0xffffffffu, ssum, off, 16);
  float aw = e / ssum;

  if (lane < 16) { s_lx[h][p] = lx; s_ly[h][p] = ly; s_aw[h][p] = aw; }
  __syncwarp(0xffffffffu);

  const int ST[4]  = {0, 4096, 5120, 5376};
  const int SZI[4] = {64, 32, 16, 8};
  float acc = 0.f;
  const float* vbase = g_value + (size_t)b*LEN*DM + h*32 + lane;

#pragma unroll
  for (int pp = 0; pp < 16; ++pp) {
    int ll = pp >> 2;
    int S  = SZI[ll];
    float x = s_lx[h][pp]*(float)S - 0.5f;
    float y = s_ly[h][pp]*(float)S - 0.5f;
    float w = s_aw[h][pp];
    float fx = floorf(x), fy = floorf(y);
    int x0 = (int)fx, y0 = (int)fy;
    float wx = x - fx, wy = y - fy;
    const float* vl = vbase + (size_t)ST[ll]*DM;
    float v00 = 0.f, v01 = 0.f, v10 = 0.f, v11 = 0.f;
    bool xa = (x0   >= 0) && (x0   < S);
    bool xb = (x0+1 >= 0) && (x0+1 < S);
    bool ya = (y0   >= 0) && (y0   < S);
    bool yb = (y0+1 >= 0) && (y0+1 < S);
    if (xa && ya) v00 = vl[(size_t)(y0*S + x0  )*DM];
    if (xb && ya) v01 = vl[(size_t)(y0*S + x0+1)*DM];
    if (xa && yb) v10 = vl[(size_t)((y0+1)*S + x0  )*DM];
    if (xb && yb) v11 = vl[(size_t)((y0+1)*S + x0+1)*DM];
    acc += w * ((v00*(1.f-wx) + v01*wx)*(1.f-wy) + (v10*(1.f-wx) + v11*wx)*wy);
  }
  __nv_bfloat16 hh = __float2bfloat16_rn(acc);
  __nv_bfloat16 ll16 = __float2bfloat16_rn(acc - __bfloat162float(hh));
  __nv_bfloat16* mh = reinterpret_cast<__nv_bfloat16*>(g_mh);
  __nv_bfloat16* ml = reinterpret_cast<__nv_bfloat16*>(g_ml);
  mh[(size_t)bq*256 + h*32 + lane] = hh;
  ml[(size_t)bq*256 + h*32 + lane] = ll16;
}

// ===========================================================================
extern "C" void kernel_launch(void* const* d_in, const int* in_sizes, int n_in,
                              void* d_out, int out_size) {
  (void)in_sizes; (void)n_in; (void)out_size;
  const float* query  = (const float*)d_in[0];
  const float* ref    = (const float*)d_in[1];
  const float* inputf = (const float*)d_in[2];
  const float* oeW    = (const float*)d_in[4];
  const float* sow    = (const float*)d_in[5];
  const float* sob    = (const float*)d_in[6];
  const float* attW   = (const float*)d_in[7];
  const float* attb   = (const float*)d_in[8];
  const float* valW   = (const float*)d_in[9];
  const float* valb   = (const float*)d_in[10];
  const float* outW   = (const float*)d_in[11];
  const float* outb   = (const float*)d_in[12];
  float* out = (float*)d_out;

  uint4 *qh,*ql,*ifh,*ifl,*mh,*ml,*wembh,*wembl,*vwh,*vwl,*owh,*owl;
  float *pval,*pofa;
  cudaGetSymbolAddress((void**)&qh, g_qh);     cudaGetSymbolAddress((void**)&ql, g_ql);
  cudaGetSymbolAddress((void**)&ifh, g_ifh);   cudaGetSymbolAddress((void**)&ifl, g_ifl);
  cudaGetSymbolAddress((void**)&mh, g_mh);     cudaGetSymbolAddress((void**)&ml, g_ml);
  cudaGetSymbolAddress((void**)&wembh, g_wembh); cudaGetSymbolAddress((void**)&wembl, g_wembl);
  cudaGetSymbolAddress((void**)&vwh, g_vwh);   cudaGetSymbolAddress((void**)&vwl, g_vwl);
  cudaGetSymbolAddress((void**)&owh, g_owh);   cudaGetSymbolAddress((void**)&owl, g_owl);
  cudaGetSymbolAddress((void**)&pval, g_value);
  cudaGetSymbolAddress((void**)&pofa, g_offaw);

  const int dynsmem = 131072 + 2*32768;  // 192 KB
  cudaFuncSetAttribute(gemm_mma<0,2>, cudaFuncAttributeMaxDynamicSharedMemorySize, dynsmem);
  cudaFuncSetAttribute(gemm_mma<1,4>, cudaFuncAttributeMaxDynamicSharedMemorySize, dynsmem);

  const int n4 = MTOT*64;
  split_rm<<<n4/256, 256>>>(reinterpret_cast<const float4*>(query),
                            reinterpret_cast<__nv_bfloat162*>(qh),
                            reinterpret_cast<__nv_bfloat162*>(ql), n4);
  split_rm<<<n4/256, 256>>>(reinterpret_cast<const float4*>(inputf),
                            reinterpret_cast<__nv_bfloat162*>(ifh),
                            reinterpret_cast<__nv_bfloat162*>(ifl), n4);
  split_rm<<<1024, 256>>>(reinterpret_cast<const float4*>(oeW),
                          reinterpret_cast<__nv_bfloat162*>(wembh),
                          reinterpret_cast<__nv_bfloat162*>(wembl), 4096*64);
  split_rm<<<64, 256>>>(reinterpret_cast<const float4*>(valW),
                        reinterpret_cast<__nv_bfloat162*>(vwh),
                        reinterpret_cast<__nv_bfloat162*>(vwl), 256*64);
  split_rm<<<64, 256>>>(reinterpret_cast<const float4*>(outW),
                        reinterpret_cast<__nv_bfloat162*>(owh),
                        reinterpret_cast<__nv_bfloat162*>(owl), 256*64);

  gemm_mma<0,2><<<dim3(MTOT/128,1), 256, dynsmem>>>(ifh, ifl, vwh, vwl, valb, nullptr, pval);
  gemm_mma<1,4><<<dim3(MTOT/128,8), 256, dynsmem>>>(qh, ql, wembh, wembl, sow, attW, pofa);
  sample_kernel<<<MTOT, 256>>>(ref, sob, attb);
  gemm_mma<0,2><<<dim3(MTOT/128,1), 256, dynsmem>>>(mh, ml, owh, owl, outb, nullptr, out);
}

// round 6
// speedup vs baseline: 2.5486x; 1.0384x over previous
#include <cuda_runtime.h>
#include <cuda_bf16.h>
#include <cuda_fp16.h>
#include <math.h>
#include <stdint.h>

#define NB   4
#define LEN  5440
#define MTOT (NB*LEN)      // 21760
#define DM   256
#define NH   8
#define NG   128

// ===========================================================================
// Scratch (allocation-free __device__ globals)
// ===========================================================================
__device__ uint4 g_qh[MTOT*32],  g_ql[MTOT*32];      // query split (row-major bf16)
__device__ uint4 g_ifh[MTOT*32], g_ifl[MTOT*32];     // input_flatten split
__device__ uint4 g_mh[MTOT*32],  g_ml[MTOT*32];      // mix (sample output) split
__device__ uint4 g_wembh[4096*32], g_wembl[4096*32]; // offset-embed W split
__device__ uint4 g_vwh[256*32],   g_vwl[256*32];     // value W split
__device__ uint4 g_owh[256*32],   g_owl[256*32];     // out W split
__device__ __half g_value[MTOT*DM];                  // value projection (fp16)
__device__ float g_offaw[(size_t)NG*MTOT*3];         // [group][row][3]

// ===========================================================================
__device__ __forceinline__ uint32_t s2u(const void* p) {
  uint32_t a;
  asm("{ .reg .u64 t; cvta.to.shared.u64 t, %1; cvt.u32.u64 %0, t; }" : "=r"(a) : "l"(p));
  return a;
}
__device__ __forceinline__ void ldsm4(uint32_t& r0, uint32_t& r1, uint32_t& r2,
                                      uint32_t& r3, uint32_t addr) {
  asm volatile("ldmatrix.sync.aligned.m8n8.x4.shared.b16 {%0,%1,%2,%3}, [%4];"
               : "=r"(r0), "=r"(r1), "=r"(r2), "=r"(r3) : "r"(addr));
}
__device__ __forceinline__ void mma16816(float& c0, float& c1, float& c2, float& c3,
                                         uint32_t a0, uint32_t a1, uint32_t a2, uint32_t a3,
                                         uint32_t b0, uint32_t b1) {
  asm volatile("mma.sync.aligned.m16n8k16.row.col.f32.bf16.bf16.f32 "
               "{%0,%1,%2,%3}, {%4,%5,%6,%7}, {%8,%9}, {%0,%1,%2,%3};"
               : "+f"(c0), "+f"(c1), "+f"(c2), "+f"(c3)
               : "r"(a0), "r"(a1), "r"(a2), "r"(a3), "r"(b0), "r"(b1));
}
#define CP_ASYNC16(dst, src) \
  asm volatile("cp.async.cg.shared.global [%0], [%1], 16;" :: "r"(dst), "l"(src))
#define CP_COMMIT() asm volatile("cp.async.commit_group;")
#define CP_WAIT(n)  asm volatile("cp.async.wait_group %0;" :: "n"(n) : "memory")

// ===========================================================================
// prep: split fp32 row-major -> bf16 hi/lo row-major
// ===========================================================================
__global__ void __launch_bounds__(256)
split_rm(const float4* __restrict__ in, __nv_bfloat162* __restrict__ hi,
         __nv_bfloat162* __restrict__ lo, int n4) {
  int i = blockIdx.x*256 + threadIdx.x;
  if (i >= n4) return;
  float4 v = in[i];
  __nv_bfloat16 hx = __float2bfloat16_rn(v.x);
  __nv_bfloat16 hy = __float2bfloat16_rn(v.y);
  __nv_bfloat16 hz = __float2bfloat16_rn(v.z);
  __nv_bfloat16 hw = __float2bfloat16_rn(v.w);
  hi[2*i+0] = __nv_bfloat162(hx, hy);
  hi[2*i+1] = __nv_bfloat162(hz, hw);
  lo[2*i+0] = __nv_bfloat162(__float2bfloat16_rn(v.x - __bfloat162float(hx)),
                             __float2bfloat16_rn(v.y - __bfloat162float(hy)));
  lo[2*i+1] = __nv_bfloat162(__float2bfloat16_rn(v.z - __bfloat162float(hz)),
                             __float2bfloat16_rn(v.w - __bfloat162float(hw)));
}

// ===========================================================================
// Split-bf16 warp-MMA GEMM. 3-stage cp.async pipeline, one sync per chunk.
// Block: 128 rows x 128 cols, 8 warps (4M x 2N), A hi|lo resident in smem.
// MODE 0: bias + fp32 store.  MODE 1: silu + group dot -> g_offaw.
// MODE 2: bias + fp16 store (value projection).
// ===========================================================================
template<int MODE, int NT>
__global__ void __launch_bounds__(256, 1)
gemm_mma(const uint4* __restrict__ Ah, const uint4* __restrict__ Al,
         const uint4* __restrict__ Bh, const uint4* __restrict__ Bl,
         const float* __restrict__ c0, const float* __restrict__ c1,
         void* __restrict__ OutV) {
  extern __shared__ char dsm[];
  const uint32_t as = s2u(dsm);            // A: 128 rows x 1024B = 131072
  const uint32_t bsb = as + 131072u;       // B: 3 x 32768
  const int tid = threadIdx.x;
  const int wid = tid >> 5, lane = tid & 31;
  const int mw = wid & 3, nw = wid >> 2;
  const int r0 = blockIdx.x * 128;
  const int N0 = blockIdx.y * NT * 128;

  // ---- load A (hi segs 0-3, lo segs 4-7 per 1KB row), swizzled ----
#pragma unroll
  for (int it = 0; it < 32; ++it) {
    int i = it*256 + tid;                  // 0..8191
    int r = i >> 6, u = i & 63;
    int half = u >> 5, uu = u & 31;
    int s = (half << 2) + (uu >> 3), c = uu & 7;
    const uint4* src = (half ? Al : Ah) + (size_t)(r0 + r)*32 + uu;
    uint32_t dst = as + (uint32_t)r*1024u + (uint32_t)s*128u + (uint32_t)((c ^ (r & 7))*16);
    CP_ASYNC16(dst, src);
  }
  CP_COMMIT();

  // lane-invariant pieces
  const int lA = mw*32 + (lane & 15);      // A row within tile
  const int jj = lane >> 4;                // 8-col group
  const int nB = nw*64 + (lane & 15);      // B row within tile
  const uint32_t pA = as + (uint32_t)lA*1024u;
  const int swA = lA & 7, swB = nB & 7;

  for (int nt = 0; nt < NT; ++nt) {
    float acc[2][8][4];
#pragma unroll
    for (int a = 0; a < 2; ++a)
#pragma unroll
      for (int b = 0; b < 8; ++b)
#pragma unroll
        for (int d = 0; d < 4; ++d) acc[a][b][d] = 0.f;

    const int nrow0 = N0 + nt*128;

    // prefetch helper (chunk-pair sc into buffer bi)
    auto prefetchB = [&](int sc, int bi) {
#pragma unroll
      for (int it = 0; it < 8; ++it) {
        int i = it*256 + tid;              // 0..2047
        int n = i >> 4, u = i & 15;
        int sub = u >> 3, c = u & 7;
        int chunk = sc*2 + sub;
        int term = chunk >> 2, c4 = chunk & 3;
        const uint4* src = ((term == 1) ? Bl : Bh) + (size_t)(nrow0 + n)*32 + c4*8 + c;
        uint32_t dst = bsb + (uint32_t)bi*32768u + (uint32_t)sub*16384u
                     + (uint32_t)n*128u + (uint32_t)((c ^ (n & 7))*16);
        CP_ASYNC16(dst, src);
      }
      CP_COMMIT();
    };

    prefetchB(0, 0);
    prefetchB(1, 1);

#pragma unroll
    for (int sc = 0; sc < 6; ++sc) {
      if (sc == 5) { CP_WAIT(0); } else { CP_WAIT(1); }
      __syncthreads();
      if (sc + 2 < 6) prefetchB(sc + 2, (sc + 2) % 3);

      const uint32_t bs = bsb + (uint32_t)(sc % 3)*32768u;
#pragma unroll
      for (int sub = 0; sub < 2; ++sub) {
        const int chunk = sc*2 + sub;
        const int term = chunk >> 2, c4 = chunk & 3;
        const int aseg = ((term == 2) ? 4 : 0) + c4;
        const uint32_t aB = pA + (uint32_t)aseg*128u;
        const uint32_t bB = bs + (uint32_t)sub*16384u + (uint32_t)nB*128u;
#pragma unroll
        for (int ks = 0; ks < 4; ++ks) {
          const int cc = ks*2 + jj;
          uint32_t a0[4], a1[4];
          ldsm4(a0[0], a0[1], a0[2], a0[3], aB + (uint32_t)((cc ^ swA)*16));
          ldsm4(a1[0], a1[1], a1[2], a1[3], aB + 16384u + (uint32_t)((cc ^ swA)*16));
          uint32_t bq[4][4];
#pragma unroll
          for (int qt = 0; qt < 4; ++qt)
            ldsm4(bq[qt][0], bq[qt][1], bq[qt][2], bq[qt][3],
                  bB + (uint32_t)qt*2048u + (uint32_t)((cc ^ swB)*16));
#pragma unroll
          for (int qt = 0; qt < 4; ++qt) {
            mma16816(acc[0][qt*2  ][0], acc[0][qt*2  ][1], acc[0][qt*2  ][2], acc[0][qt*2  ][3],
                     a0[0], a0[1], a0[2], a0[3], bq[qt][0], bq[qt][2]);
            mma16816(acc[0][qt*2+1][0], acc[0][qt*2+1][1], acc[0][qt*2+1][2], acc[0][qt*2+1][3],
                     a0[0], a0[1], a0[2], a0[3], bq[qt][1], bq[qt][3]);
            mma16816(acc[1][qt*2  ][0], acc[1][qt*2  ][1], acc[1][qt*2  ][2], acc[1][qt*2  ][3],
                     a1[0], a1[1], a1[2], a1[3], bq[qt][0], bq[qt][2]);
            mma16816(acc[1][qt*2+1][0], acc[1][qt*2+1][1], acc[1][qt*2+1][2], acc[1][qt*2+1][3],
                     a1[0], a1[1], a1[2], a1[3], bq[qt][1], bq[qt][3]);
          }
        }
      }
    }

    // ---- epilogue ----
    if (MODE == 0 || MODE == 2) {
#pragma unroll
      for (int mt = 0; mt < 2; ++mt)
#pragma unroll
        for (int h = 0; h < 2; ++h) {
          int row = r0 + mw*32 + mt*16 + (lane >> 2) + h*8;
#pragma unroll
          for (int j = 0; j < 8; ++j) {
            int col = nt*128 + nw*64 + j*8 + (lane & 3)*2;
            float ox = acc[mt][j][h*2+0] + c0[col];
            float oy = acc[mt][j][h*2+1] + c0[col+1];
            if (MODE == 0) {
              float2 o; o.x = ox; o.y = oy;
              *reinterpret_cast<float2*>((float*)OutV + (size_t)row*256 + col) = o;
            } else {
              __half2 o = __floats2half2_rn(ox, oy);
              *reinterpret_cast<__half2*>((__half*)OutV + (size_t)row*256 + col) = o;
            }
          }
        }
    } else {
      const float2* sw2 = reinterpret_cast<const float2*>(c0);
      float* Out = (float*)OutV;
#pragma unroll
      for (int grp = 0; grp < 2; ++grp) {
        int g = (N0 + nt*128 + nw*64 + grp*32) >> 5;
        float wx[4][2], wy[4][2], wl[4][2];
#pragma unroll
        for (int j = 0; j < 4; ++j) {
          int col = g*32 + j*8 + (lane & 3)*2;
          float2 q0 = __ldg(&sw2[col]), q1 = __ldg(&sw2[col+1]);
          wx[j][0] = q0.x; wy[j][0] = q0.y;
          wx[j][1] = q1.x; wy[j][1] = q1.y;
          wl[j][0] = __ldg(&c1[col]); wl[j][1] = __ldg(&c1[col+1]);
        }
#pragma unroll
        for (int mt = 0; mt < 2; ++mt)
#pragma unroll
          for (int h = 0; h < 2; ++h) {
            int row = r0 + mw*32 + mt*16 + (lane >> 2) + h*8;
            float sx = 0.f, sy = 0.f, sl = 0.f;
#pragma unroll
            for (int j = 0; j < 4; ++j) {
              float v0 = acc[mt][grp*4+j][h*2+0];
              float v1 = acc[mt][grp*4+j][h*2+1];
              v0 = v0 / (1.f + __expf(-v0));
              v1 = v1 / (1.f + __expf(-v1));
              sx = fmaf(v0, wx[j][0], sx); sx = fmaf(v1, wx[j][1], sx);
              sy = fmaf(v0, wy[j][0], sy); sy = fmaf(v1, wy[j][1], sy);
              sl = fmaf(v0, wl[j][0], sl); sl = fmaf(v1, wl[j][1], sl);
            }
            sx += __shfl_xor_sync(0xffffffffu, sx, 1);
            sy += __shfl_xor_sync(0xffffffffu, sy, 1);
            sl += __shfl_xor_sync(0xffffffffu, sl, 1);
            sx += __shfl_xor_sync(0xffffffffu, sx, 2);
            sy += __shfl_xor_sync(0xffffffffu, sy, 2);
            sl += __shfl_xor_sync(0xffffffffu, sl, 2);
            if ((lane & 3) == 0) {
              float* o = Out + ((size_t)g*MTOT + row)*3;
              o[0] = sx; o[1] = sy; o[2] = sl;
            }
          }
      }
    }
  }
}

// ===========================================================================
// Sampling: one warp per (b,q,head). fp16 value gathers (half the traffic).
// ===========================================================================
__global__ void __launch_bounds__(256)
sample_kernel(const float* __restrict__ ref, const float* __restrict__ sob,
              const float* __restrict__ attb) {
  __shared__ float s_lx[NH][16], s_ly[NH][16], s_aw[NH][16];
  const int bq   = blockIdx.x;
  const int b    = bq / LEN;
  const int h    = threadIdx.x >> 5;
  const int lane = threadIdx.x & 31;
  const int p    = lane & 15;
  const int l    = p >> 2;

  const float SZ[4] = {64.f, 32.f, 16.f, 8.f};
  int g = h*16 + p;
  size_t ob = ((size_t)g*MTOT + bq)*3;
  float rx = g_offaw[ob+0], ry = g_offaw[ob+1], rl = g_offaw[ob+2];
  float inv = 1.f / SZ[l];
  float lx = ref[(size_t)bq*8 + l*2 + 0] + (rx + sob[g*2+0]) * inv;
  float ly = ref[(size_t)bq*8 + l*2 + 1] + (ry + sob[g*2+1]) * inv;
  float logit = rl + attb[g];

  float mx = logit;
#pragma unroll
  for (int off = 8; off; off >>= 1)
    mx = fmaxf(mx, __shfl_xor_sync(0xffffffffu, mx, off, 16));
  float e = __expf(logit - mx);
  float ssum = e;
#pragma unroll
  for (int off = 8; off; off >>= 1)
    ssum += __shfl_xor_sync(0xffffffffu, ssum, off, 16);
  float aw = e / ssum;

  if (lane < 16) { s_lx[h][p] = lx; s_ly[h][p] = ly; s_aw[h][p] = aw; }
  __syncwarp(0xffffffffu);

  const int ST[4]  = {0, 4096, 5120, 5376};
  const int SZI[4] = {64, 32, 16, 8};
  float acc = 0.f;
  const __half* vbase = g_value + (size_t)b*LEN*DM + h*32 + lane;

#pragma unroll
  for (int pp = 0; pp < 16; ++pp) {
    int ll = pp >> 2;
    int S  = SZI[ll];
    float x = s_lx[h][pp]*(float)S - 0.5f;
    float y = s_ly[h][pp]*(float)S - 0.5f;
    float w = s_aw[h][pp];
    float fx = floorf(x), fy = floorf(y);
    int x0 = (int)fx, y0 = (int)fy;
    float wx = x - fx, wy = y - fy;
    const __half* vl = vbase + (size_t)ST[ll]*DM;
    float v00 = 0.f, v01 = 0.f, v10 = 0.f, v11 = 0.f;
    bool xa = (x0   >= 0) && (x0   < S);
    bool xb = (x0+1 >= 0) && (x0+1 < S);
    bool ya = (y0   >= 0) && (y0   < S);
    bool yb = (y0+1 >= 0) && (y0+1 < S);
    if (xa && ya) v00 = __half2float(vl[(size_t)(y0*S + x0  )*DM]);
    if (xb && ya) v01 = __half2float(vl[(size_t)(y0*S + x0+1)*DM]);
    if (xa && yb) v10 = __half2float(vl[(size_t)((y0+1)*S + x0  )*DM]);
    if (xb && yb) v11 = __half2float(vl[(size_t)((y0+1)*S + x0+1)*DM]);
    acc += w * ((v00*(1.f-wx) + v01*wx)*(1.f-wy) + (v10*(1.f-wx) + v11*wx)*wy);
  }
  __nv_bfloat16 hh = __float2bfloat16_rn(acc);
  __nv_bfloat16 ll16 = __float2bfloat16_rn(acc - __bfloat162float(hh));
  __nv_bfloat16* mh = reinterpret_cast<__nv_bfloat16*>(g_mh);
  __nv_bfloat16* ml = reinterpret_cast<__nv_bfloat16*>(g_ml);
  mh[(size_t)bq*256 + h*32 + lane] = hh;
  ml[(size_t)bq*256 + h*32 + lane] = ll16;
}

// ===========================================================================
extern "C" void kernel_launch(void* const* d_in, const int* in_sizes, int n_in,
                              void* d_out, int out_size) {
  (void)in_sizes; (void)n_in; (void)out_size;
  const float* query  = (const float*)d_in[0];
  const float* ref    = (const float*)d_in[1];
  const float* inputf = (const float*)d_in[2];
  const float* oeW    = (const float*)d_in[4];
  const float* sow    = (const float*)d_in[5];
  const float* sob    = (const float*)d_in[6];
  const float* attW   = (const float*)d_in[7];
  const float* attb   = (const float*)d_in[8];
  const float* valW   = (const float*)d_in[9];
  const float* valb   = (const float*)d_in[10];
  const float* outW   = (const float*)d_in[11];
  const float* outb   = (const float*)d_in[12];
  float* out = (float*)d_out;

  uint4 *qh,*ql,*ifh,*ifl,*mh,*ml,*wembh,*wembl,*vwh,*vwl,*owh,*owl;
  void *pval; float *pofa;
  cudaGetSymbolAddress((void**)&qh, g_qh);     cudaGetSymbolAddress((void**)&ql, g_ql);
  cudaGetSymbolAddress((void**)&ifh, g_ifh);   cudaGetSymbolAddress((void**)&ifl, g_ifl);
  cudaGetSymbolAddress((void**)&mh, g_mh);     cudaGetSymbolAddress((void**)&ml, g_ml);
  cudaGetSymbolAddress((void**)&wembh, g_wembh); cudaGetSymbolAddress((void**)&wembl, g_wembl);
  cudaGetSymbolAddress((void**)&vwh, g_vwh);   cudaGetSymbolAddress((void**)&vwl, g_vwl);
  cudaGetSymbolAddress((void**)&owh, g_owh);   cudaGetSymbolAddress((void**)&owl, g_owl);
  cudaGetSymbolAddress((void**)&pval, g_value);
  cudaGetSymbolAddress((void**)&pofa, g_offaw);

  const int dynsmem = 131072 + 3*32768;  // 224 KB
  cudaFuncSetAttribute(gemm_mma<0,2>, cudaFuncAttributeMaxDynamicSharedMemorySize, dynsmem);
  cudaFuncSetAttribute(gemm_mma<1,4>, cudaFuncAttributeMaxDynamicSharedMemorySize, dynsmem);
  cudaFuncSetAttribute(gemm_mma<2,2>, cudaFuncAttributeMaxDynamicSharedMemorySize, dynsmem);

  const int n4 = MTOT*64;
  // launch order arranged so ncu (-s 5) captures the offset GEMM (index 5)
  split_rm<<<n4/256, 256>>>(reinterpret_cast<const float4*>(query),
                            reinterpret_cast<__nv_bfloat162*>(qh),
                            reinterpret_cast<__nv_bfloat162*>(ql), n4);
  split_rm<<<1024, 256>>>(reinterpret_cast<const float4*>(oeW),
                          reinterpret_cast<__nv_bfloat162*>(wembh),
                          reinterpret_cast<__nv_bfloat162*>(wembl), 4096*64);
  split_rm<<<n4/256, 256>>>(reinterpret_cast<const float4*>(inputf),
                            reinterpret_cast<__nv_bfloat162*>(ifh),
                            reinterpret_cast<__nv_bfloat162*>(ifl), n4);
  split_rm<<<64, 256>>>(reinterpret_cast<const float4*>(valW),
                        reinterpret_cast<__nv_bfloat162*>(vwh),
                        reinterpret_cast<__nv_bfloat162*>(vwl), 256*64);
  split_rm<<<64, 256>>>(reinterpret_cast<const float4*>(outW),
                        reinterpret_cast<__nv_bfloat162*>(owh),
                        reinterpret_cast<__nv_bfloat162*>(owl), 256*64);

  gemm_mma<1,4><<<dim3(MTOT/128,8), 256, dynsmem>>>(qh, ql, wembh, wembl, sow, attW, pofa);
  gemm_mma<2,2><<<dim3(MTOT/128,1), 256, dynsmem>>>(ifh, ifl, vwh, vwl, valb, nullptr, pval);
  sample_kernel<<<MTOT, 256>>>(ref, sob, attb);
  gemm_mma<0,2><<<dim3(MTOT/128,1), 256, dynsmem>>>(mh, ml, owh, owl, outb, nullptr, out);
}

// round 7
// speedup vs baseline: 2.5620x; 1.0053x over previous
#include <cuda_runtime.h>
#include <cuda_bf16.h>
#include <cuda_fp16.h>
#include <math.h>
#include <stdint.h>

#define NB   4
#define LEN  5440
#define MTOT (NB*LEN)      // 21760
#define DM   256
#define NH   8
#define NG   128

// ===========================================================================
// Scratch (allocation-free __device__ globals)
// ===========================================================================
__device__ uint4 g_qh[MTOT*32],  g_ql[MTOT*32];      // query split (row-major bf16)
__device__ uint4 g_ifh[MTOT*32], g_ifl[MTOT*32];     // input_flatten split
__device__ uint4 g_mh[MTOT*32],  g_ml[MTOT*32];      // mix (sample output) split
__device__ uint4 g_wembh[4096*32], g_wembl[4096*32]; // offset-embed W split
__device__ uint4 g_vwh[256*32],   g_vwl[256*32];     // value W split
__device__ uint4 g_owh[256*32],   g_owl[256*32];     // out W split
__device__ __half g_value[MTOT*DM];                  // value projection (fp16)
__device__ float g_offaw[(size_t)NG*MTOT*3];         // [group][row][3]

// ===========================================================================
__device__ __forceinline__ uint32_t s2u(const void* p) {
  uint32_t a;
  asm("{ .reg .u64 t; cvta.to.shared.u64 t, %1; cvt.u32.u64 %0, t; }" : "=r"(a) : "l"(p));
  return a;
}
__device__ __forceinline__ void ldsm4(uint32_t& r0, uint32_t& r1, uint32_t& r2,
                                      uint32_t& r3, uint32_t addr) {
  asm volatile("ldmatrix.sync.aligned.m8n8.x4.shared.b16 {%0,%1,%2,%3}, [%4];"
               : "=r"(r0), "=r"(r1), "=r"(r2), "=r"(r3) : "r"(addr));
}
__device__ __forceinline__ void mma16816(float& c0, float& c1, float& c2, float& c3,
                                         uint32_t a0, uint32_t a1, uint32_t a2, uint32_t a3,
                                         uint32_t b0, uint32_t b1) {
  asm volatile("mma.sync.aligned.m16n8k16.row.col.f32.bf16.bf16.f32 "
               "{%0,%1,%2,%3}, {%4,%5,%6,%7}, {%8,%9}, {%0,%1,%2,%3};"
               : "+f"(c0), "+f"(c1), "+f"(c2), "+f"(c3)
               : "r"(a0), "r"(a1), "r"(a2), "r"(a3), "r"(b0), "r"(b1));
}
#define CP_ASYNC16(dst, src) \
  asm volatile("cp.async.cg.shared.global [%0], [%1], 16;" :: "r"(dst), "l"(src))
#define CP_COMMIT() asm volatile("cp.async.commit_group;")
#define CP_WAIT(n)  asm volatile("cp.async.wait_group %0;" :: "n"(n) : "memory")

// ===========================================================================
// prep: split fp32 row-major -> bf16 hi/lo row-major
// ===========================================================================
__device__ __forceinline__ void split_body(const float4* __restrict__ in,
                                           __nv_bfloat162* __restrict__ hi,
                                           __nv_bfloat162* __restrict__ lo, int i) {
  float4 v = in[i];
  __nv_bfloat16 hx = __float2bfloat16_rn(v.x);
  __nv_bfloat16 hy = __float2bfloat16_rn(v.y);
  __nv_bfloat16 hz = __float2bfloat16_rn(v.z);
  __nv_bfloat16 hw = __float2bfloat16_rn(v.w);
  hi[2*i+0] = __nv_bfloat162(hx, hy);
  hi[2*i+1] = __nv_bfloat162(hz, hw);
  lo[2*i+0] = __nv_bfloat162(__float2bfloat16_rn(v.x - __bfloat162float(hx)),
                             __float2bfloat16_rn(v.y - __bfloat162float(hy)));
  lo[2*i+1] = __nv_bfloat162(__float2bfloat16_rn(v.z - __bfloat162float(hz)),
                             __float2bfloat16_rn(v.w - __bfloat162float(hw)));
}

__global__ void __launch_bounds__(256)
split_rm(const float4* __restrict__ in, __nv_bfloat162* __restrict__ hi,
         __nv_bfloat162* __restrict__ lo, int n4) {
  int i = blockIdx.x*256 + threadIdx.x;
  if (i >= n4) return;
  split_body(in, hi, lo, i);
}

// fused split of the two 256x256 weights (one launch, 128 blocks)
__global__ void __launch_bounds__(256)
split_w2(const float4* __restrict__ w1, __nv_bfloat162* __restrict__ h1,
         __nv_bfloat162* __restrict__ l1,
         const float4* __restrict__ w2, __nv_bfloat162* __restrict__ h2,
         __nv_bfloat162* __restrict__ l2) {
  int b = blockIdx.x;
  if (b < 64) split_body(w1, h1, l1, b*256 + threadIdx.x);
  else        split_body(w2, h2, l2, (b-64)*256 + threadIdx.x);
}

// ===========================================================================
// Split-bf16 warp-MMA GEMM, chunk-major mainloop:
// for each 128-col k-chunk c4: load Bh[c4]+Bl[c4] (32KB) once, run 3 term
// passes (Ah*Bh, Al*Bh, Ah*Bl).  B global traffic 2/3 of term-major order.
// Block: 128 rows x 128 cols, 8 warps (4M x 2N), A hi|lo resident in smem.
// MODE 0: bias + fp32 store.  MODE 1: silu + group dot -> g_offaw.
// MODE 2: bias + fp16 store (value projection).
// ===========================================================================
template<int MODE, int NT>
__global__ void __launch_bounds__(256, 1)
gemm_mma(const uint4* __restrict__ Ah, const uint4* __restrict__ Al,
         const uint4* __restrict__ Bh, const uint4* __restrict__ Bl,
         const float* __restrict__ c0, const float* __restrict__ c1,
         void* __restrict__ OutV) {
  extern __shared__ char dsm[];
  const uint32_t as = s2u(dsm);            // A: 128 rows x 1024B = 131072
  const uint32_t bsb = as + 131072u;       // B: 3 x 32768 (hi 16KB | lo 16KB)
  const int tid = threadIdx.x;
  const int wid = tid >> 5, lane = tid & 31;
  const int mw = wid & 3, nw = wid >> 2;
  const int r0 = blockIdx.x * 128;
  const int N0 = blockIdx.y * NT * 128;

  // ---- load A (hi segs 0-3, lo segs 4-7 per 1KB row), swizzled ----
#pragma unroll
  for (int it = 0; it < 32; ++it) {
    int i = it*256 + tid;                  // 0..8191
    int r = i >> 6, u = i & 63;
    int half = u >> 5, uu = u & 31;
    int s = (half << 2) + (uu >> 3), c = uu & 7;
    const uint4* src = (half ? Al : Ah) + (size_t)(r0 + r)*32 + uu;
    uint32_t dst = as + (uint32_t)r*1024u + (uint32_t)s*128u + (uint32_t)((c ^ (r & 7))*16);
    CP_ASYNC16(dst, src);
  }
  CP_COMMIT();

  // lane-invariant pieces
  const int lA = mw*32 + (lane & 15);      // A row within tile
  const int jj = lane >> 4;                // 8-col group
  const int nB = nw*64 + (lane & 15);      // B row within tile
  const uint32_t pA = as + (uint32_t)lA*1024u;
  const int swA = lA & 7, swB = nB & 7;

  for (int nt = 0; nt < NT; ++nt) {
    float acc[2][8][4];
#pragma unroll
    for (int a = 0; a < 2; ++a)
#pragma unroll
      for (int b = 0; b < 8; ++b)
#pragma unroll
        for (int d = 0; d < 4; ++d) acc[a][b][d] = 0.f;

    const int nrow0 = N0 + nt*128;

    // prefetch k-chunk c4 (Bh 16KB + Bl 16KB) into buffer bi
    auto prefetchC4 = [&](int c4, int bi) {
#pragma unroll
      for (int it = 0; it < 8; ++it) {
        int i = it*256 + tid;              // 0..2047
        int n = i >> 4, u = i & 15;
        int sub = u >> 3, c = u & 7;       // sub: 0=hi, 1=lo
        const uint4* src = (sub ? Bl : Bh) + (size_t)(nrow0 + n)*32 + c4*8 + c;
        uint32_t dst = bsb + (uint32_t)bi*32768u + (uint32_t)sub*16384u
                     + (uint32_t)n*128u + (uint32_t)((c ^ (n & 7))*16);
        CP_ASYNC16(dst, src);
      }
      CP_COMMIT();
    };

    prefetchC4(0, 0);
    prefetchC4(1, 1);

#pragma unroll
    for (int c4 = 0; c4 < 4; ++c4) {
      if (c4 == 3) { CP_WAIT(0); } else { CP_WAIT(1); }
      __syncthreads();
      if (c4 + 2 < 4) prefetchC4(c4 + 2, (c4 + 2) % 3);

      const uint32_t bs  = bsb + (uint32_t)(c4 % 3)*32768u;
      const uint32_t aBh = pA + (uint32_t)c4*128u;
      const uint32_t aBl = pA + (uint32_t)(4 + c4)*128u;
#pragma unroll
      for (int ks = 0; ks < 4; ++ks) {
        const int cc = ks*2 + jj;
        const uint32_t csw = (uint32_t)((cc ^ swA)*16);
        uint32_t ah[2][4], al[2][4];
        ldsm4(ah[0][0], ah[0][1], ah[0][2], ah[0][3], aBh + csw);
        ldsm4(ah[1][0], ah[1][1], ah[1][2], ah[1][3], aBh + 16384u + csw);
        ldsm4(al[0][0], al[0][1], al[0][2], al[0][3], aBl + csw);
        ldsm4(al[1][0], al[1][1], al[1][2], al[1][3], aBl + 16384u + csw);
        const uint32_t bsw = (uint32_t)((cc ^ swB)*16);
        uint32_t bh[4][4], bl[4][4];
#pragma unroll
        for (int qt = 0; qt < 4; ++qt) {
          ldsm4(bh[qt][0], bh[qt][1], bh[qt][2], bh[qt][3],
                bs + (uint32_t)nB*128u + (uint32_t)qt*2048u + bsw);
          ldsm4(bl[qt][0], bl[qt][1], bl[qt][2], bl[qt][3],
                bs + 16384u + (uint32_t)nB*128u + (uint32_t)qt*2048u + bsw);
        }
#pragma unroll
        for (int qt = 0; qt < 4; ++qt) {
#pragma unroll
          for (int mt = 0; mt < 2; ++mt) {
            // Ah * Bh
            mma16816(acc[mt][qt*2  ][0], acc[mt][qt*2  ][1], acc[mt][qt*2  ][2], acc[mt][qt*2  ][3],
                     ah[mt][0], ah[mt][1], ah[mt][2], ah[mt][3], bh[qt][0], bh[qt][2]);
            mma16816(acc[mt][qt*2+1][0], acc[mt][qt*2+1][1], acc[mt][qt*2+1][2], acc[mt][qt*2+1][3],
                     ah[mt][0], ah[mt][1], ah[mt][2], ah[mt][3], bh[qt][1], bh[qt][3]);
            // Al * Bh
            mma16816(acc[mt][qt*2  ][0], acc[mt][qt*2  ][1], acc[mt][qt*2  ][2], acc[mt][qt*2  ][3],
                     al[mt][0], al[mt][1], al[mt][2], al[mt][3], bh[qt][0], bh[qt][2]);
            mma16816(acc[mt][qt*2+1][0], acc[mt][qt*2+1][1], acc[mt][qt*2+1][2], acc[mt][qt*2+1][3],
                     al[mt][0], al[mt][1], al[mt][2], al[mt][3], bh[qt][1], bh[qt][3]);
            // Ah * Bl
            mma16816(acc[mt][qt*2  ][0], acc[mt][qt*2  ][1], acc[mt][qt*2  ][2], acc[mt][qt*2  ][3],
                     ah[mt][0], ah[mt][1], ah[mt][2], ah[mt][3], bl[qt][0], bl[qt][2]);
            mma16816(acc[mt][qt*2+1][0], acc[mt][qt*2+1][1], acc[mt][qt*2+1][2], acc[mt][qt*2+1][3],
                     ah[mt][0], ah[mt][1], ah[mt][2], ah[mt][3], bl[qt][1], bl[qt][3]);
          }
        }
      }
    }
    __syncthreads();   // protect buf0 from next nt's prefetch

    // ---- epilogue ----
    if (MODE == 0 || MODE == 2) {
#pragma unroll
      for (int mt = 0; mt < 2; ++mt)
#pragma unroll
        for (int h = 0; h < 2; ++h) {
          int row = r0 + mw*32 + mt*16 + (lane >> 2) + h*8;
#pragma unroll
          for (int j = 0; j < 8; ++j) {
            int col = nt*128 + nw*64 + j*8 + (lane & 3)*2;
            float ox = acc[mt][j][h*2+0] + c0[col];
            float oy = acc[mt][j][h*2+1] + c0[col+1];
            if (MODE == 0) {
              float2 o; o.x = ox; o.y = oy;
              *reinterpret_cast<float2*>((float*)OutV + (size_t)row*256 + col) = o;
            } else {
              __half2 o = __floats2half2_rn(ox, oy);
              *reinterpret_cast<__half2*>((__half*)OutV + (size_t)row*256 + col) = o;
            }
          }
        }
    } else {
      const float2* sw2 = reinterpret_cast<const float2*>(c0);
      float* Out = (float*)OutV;
#pragma unroll
      for (int grp = 0; grp < 2; ++grp) {
        int g = (N0 + nt*128 + nw*64 + grp*32) >> 5;
        float wx[4][2], wy[4][2], wl[4][2];
#pragma unroll
        for (int j = 0; j < 4; ++j) {
          int col = g*32 + j*8 + (lane & 3)*2;
          float2 q0 = __ldg(&sw2[col]), q1 = __ldg(&sw2[col+1]);
          wx[j][0] = q0.x; wy[j][0] = q0.y;
          wx[j][1] = q1.x; wy[j][1] = q1.y;
          wl[j][0] = __ldg(&c1[col]); wl[j][1] = __ldg(&c1[col+1]);
        }
#pragma unroll
        for (int mt = 0; mt < 2; ++mt)
#pragma unroll
          for (int h = 0; h < 2; ++h) {
            int row = r0 + mw*32 + mt*16 + (lane >> 2) + h*8;
            float sx = 0.f, sy = 0.f, sl = 0.f;
#pragma unroll
            for (int j = 0; j < 4; ++j) {
              float v0 = acc[mt][grp*4+j][h*2+0];
              float v1 = acc[mt][grp*4+j][h*2+1];
              v0 = v0 / (1.f + __expf(-v0));
              v1 = v1 / (1.f + __expf(-v1));
              sx = fmaf(v0, wx[j][0], sx); sx = fmaf(v1, wx[j][1], sx);
              sy = fmaf(v0, wy[j][0], sy); sy = fmaf(v1, wy[j][1], sy);
              sl = fmaf(v0, wl[j][0], sl); sl = fmaf(v1, wl[j][1], sl);
            }
            sx += __shfl_xor_sync(0xffffffffu, sx, 1);
            sy += __shfl_xor_sync(0xffffffffu, sy, 1);
            sl += __shfl_xor_sync(0xffffffffu, sl, 1);
            sx += __shfl_xor_sync(0xffffffffu, sx, 2);
            sy += __shfl_xor_sync(0xffffffffu, sy, 2);
            sl += __shfl_xor_sync(0xffffffffu, sl, 2);
            if ((lane & 3) == 0) {
              float* o = Out + ((size_t)g*MTOT + row)*3;
              o[0] = sx; o[1] = sy; o[2] = sl;
            }
          }
      }
    }
  }
}

// ===========================================================================
// Sampling: one warp per (b,q,head). fp16 value gathers.
// ===========================================================================
__global__ void __launch_bounds__(256)
sample_kernel(const float* __restrict__ ref, const float* __restrict__ sob,
              const float* __restrict__ attb) {
  __shared__ float s_lx[NH][16], s_ly[NH][16], s_aw[NH][16];
  const int bq   = blockIdx.x;
  const int b    = bq / LEN;
  const int h    = threadIdx.x >> 5;
  const int lane = threadIdx.x & 31;
  const int p    = lane & 15;
  const int l    = p >> 2;

  const float SZ[4] = {64.f, 32.f, 16.f, 8.f};
  int g = h*16 + p;
  size_t ob = ((size_t)g*MTOT + bq)*3;
  float rx = g_offaw[ob+0], ry = g_offaw[ob+1], rl = g_offaw[ob+2];
  float inv = 1.f / SZ[l];
  float lx = ref[(size_t)bq*8 + l*2 + 0] + (rx + sob[g*2+0]) * inv;
  float ly = ref[(size_t)bq*8 + l*2 + 1] + (ry + sob[g*2+1]) * inv;
  float logit = rl + attb[g];

  float mx = logit;
#pragma unroll
  for (int off = 8; off; off >>= 1)
    mx = fmaxf(mx, __shfl_xor_sync(0xffffffffu, mx, off, 16));
  float e = __expf(logit - mx);
  float ssum = e;
#pragma unroll
  for (int off = 8; off; off >>= 1)
    ssum += __shfl_xor_sync(0xffffffffu, ssum, off, 16);
  float aw = e / ssum;

  if (lane < 16) { s_lx[h][p] = lx; s_ly[h][p] = ly; s_aw[h][p] = aw; }
  __syncwarp(0xffffffffu);

  const int ST[4]  = {0, 4096, 5120, 5376};
  const int SZI[4] = {64, 32, 16, 8};
  float acc = 0.f;
  const __half* vbase = g_value + (size_t)b*LEN*DM + h*32 + lane;

#pragma unroll
  for (int pp = 0; pp < 16; ++pp) {
    int ll = pp >> 2;
    int S  = SZI[ll];
    float x = s_lx[h][pp]*(float)S - 0.5f;
    float y = s_ly[h][pp]*(float)S - 0.5f;
    float w = s_aw[h][pp];
    float fx = floorf(x), fy = floorf(y);
    int x0 = (int)fx, y0 = (int)fy;
    float wx = x - fx, wy = y - fy;
    const __half* vl = vbase + (size_t)ST[ll]*DM;
    float v00 = 0.f, v01 = 0.f, v10 = 0.f, v11 = 0.f;
    bool xa = (x0   >= 0) && (x0   < S);
    bool xb = (x0+1 >= 0) && (x0+1 < S);
    bool ya = (y0   >= 0) && (y0   < S);
    bool yb = (y0+1 >= 0) && (y0+1 < S);
    if (xa && ya) v00 = __half2float(vl[(size_t)(y0*S + x0  )*DM]);
    if (xb && ya) v01 = __half2float(vl[(size_t)(y0*S + x0+1)*DM]);
    if (xa && yb) v10 = __half2float(vl[(size_t)((y0+1)*S + x0  )*DM]);
    if (xb && yb) v11 = __half2float(vl[(size_t)((y0+1)*S + x0+1)*DM]);
    acc += w * ((v00*(1.f-wx) + v01*wx)*(1.f-wy) + (v10*(1.f-wx) + v11*wx)*wy);
  }
  __nv_bfloat16 hh = __float2bfloat16_rn(acc);
  __nv_bfloat16 ll16 = __float2bfloat16_rn(acc - __bfloat162float(hh));
  __nv_bfloat16* mh = reinterpret_cast<__nv_bfloat16*>(g_mh);
  __nv_bfloat16* ml = reinterpret_cast<__nv_bfloat16*>(g_ml);
  mh[(size_t)bq*256 + h*32 + lane] = hh;
  ml[(size_t)bq*256 + h*32 + lane] = ll16;
}

// ===========================================================================
extern "C" void kernel_launch(void* const* d_in, const int* in_sizes, int n_in,
                              void* d_out, int out_size) {
  (void)in_sizes; (void)n_in; (void)out_size;
  const float* query  = (const float*)d_in[0];
  const float* ref    = (const float*)d_in[1];
  const float* inputf = (const float*)d_in[2];
  const float* oeW    = (const float*)d_in[4];
  const float* sow    = (const float*)d_in[5];
  const float* sob    = (const float*)d_in[6];
  const float* attW   = (const float*)d_in[7];
  const float* attb   = (const float*)d_in[8];
  const float* valW   = (const float*)d_in[9];
  const float* valb   = (const float*)d_in[10];
  const float* outW   = (const float*)d_in[11];
  const float* outb   = (const float*)d_in[12];
  float* out = (float*)d_out;

  uint4 *qh,*ql,*ifh,*ifl,*mh,*ml,*wembh,*wembl,*vwh,*vwl,*owh,*owl;
  void *pval; float *pofa;
  cudaGetSymbolAddress((void**)&qh, g_qh);     cudaGetSymbolAddress((void**)&ql, g_ql);
  cudaGetSymbolAddress((void**)&ifh, g_ifh);   cudaGetSymbolAddress((void**)&ifl, g_ifl);
  cudaGetSymbolAddress((void**)&mh, g_mh);     cudaGetSymbolAddress((void**)&ml, g_ml);
  cudaGetSymbolAddress((void**)&wembh, g_wembh); cudaGetSymbolAddress((void**)&wembl, g_wembl);
  cudaGetSymbolAddress((void**)&vwh, g_vwh);   cudaGetSymbolAddress((void**)&vwl, g_vwl);
  cudaGetSymbolAddress((void**)&owh, g_owh);   cudaGetSymbolAddress((void**)&owl, g_owl);
  cudaGetSymbolAddress((void**)&pval, g_value);
  cudaGetSymbolAddress((void**)&pofa, g_offaw);

  const int dynsmem = 131072 + 3*32768;  // 224 KB
  cudaFuncSetAttribute(gemm_mma<0,2>, cudaFuncAttributeMaxDynamicSharedMemorySize, dynsmem);
  cudaFuncSetAttribute(gemm_mma<1,4>, cudaFuncAttributeMaxDynamicSharedMemorySize, dynsmem);
  cudaFuncSetAttribute(gemm_mma<2,2>, cudaFuncAttributeMaxDynamicSharedMemorySize, dynsmem);

  const int n4 = MTOT*64;
  // launch order: offset GEMM at our 0-based index 4 (ncu -s 5 with one
  // harness launch ahead of ours should capture it)
  split_rm<<<n4/256, 256>>>(reinterpret_cast<const float4*>(query),
                            reinterpret_cast<__nv_bfloat162*>(qh),
                            reinterpret_cast<__nv_bfloat162*>(ql), n4);
  split_rm<<<1024, 256>>>(reinterpret_cast<const float4*>(oeW),
                          reinterpret_cast<__nv_bfloat162*>(wembh),
                          reinterpret_cast<__nv_bfloat162*>(wembl), 4096*64);
  split_rm<<<n4/256, 256>>>(reinterpret_cast<const float4*>(inputf),
                            reinterpret_cast<__nv_bfloat162*>(ifh),
                            reinterpret_cast<__nv_bfloat162*>(ifl), n4);
  split_w2<<<128, 256>>>(reinterpret_cast<const float4*>(valW),
                         reinterpret_cast<__nv_bfloat162*>(vwh),
                         reinterpret_cast<__nv_bfloat162*>(vwl),
                         reinterpret_cast<const float4*>(outW),
                         reinterpret_cast<__nv_bfloat162*>(owh),
                         reinterpret_cast<__nv_bfloat162*>(owl));

  gemm_mma<1,4><<<dim3(MTOT/128,8), 256, dynsmem>>>(qh, ql, wembh, wembl, sow, attW, pofa);
  gemm_mma<2,2><<<dim3(MTOT/128,1), 256, dynsmem>>>(ifh, ifl, vwh, vwl, valb, nullptr, pval);
  sample_kernel<<<MTOT, 256>>>(ref, sob, attb);
  gemm_mma<0,2><<<dim3(MTOT/128,1), 256, dynsmem>>>(mh, ml, owh, owl, outb, nullptr, out);
}

// round 8
// speedup vs baseline: 2.6106x; 1.0190x over previous
#include <cuda_runtime.h>
#include <cuda_bf16.h>
#include <cuda_fp16.h>
#include <math.h>
#include <stdint.h>

#define NB   4
#define LEN  5440
#define MTOT (NB*LEN)      // 21760
#define DM   256
#define NH   8
#define NG   128

// ===========================================================================
// Scratch (allocation-free __device__ globals)
// ===========================================================================
__device__ uint4 g_qh[MTOT*32],  g_ql[MTOT*32];      // query split (row-major bf16)
__device__ uint4 g_ifh[MTOT*32], g_ifl[MTOT*32];     // input_flatten split
__device__ uint4 g_mh[MTOT*32],  g_ml[MTOT*32];      // mix (sample output) split
__device__ uint4 g_wembh[4096*32], g_wembl[4096*32]; // offset-embed W split
__device__ uint4 g_vwh[256*32],   g_vwl[256*32];     // value W split
__device__ uint4 g_owh[256*32],   g_owl[256*32];     // out W split
__device__ __half g_value[MTOT*DM];                  // value projection (fp16)
__device__ float g_offaw[(size_t)NG*MTOT*3];         // [group][row][3]

// ===========================================================================
__device__ __forceinline__ uint32_t s2u(const void* p) {
  uint32_t a;
  asm("{ .reg .u64 t; cvta.to.shared.u64 t, %1; cvt.u32.u64 %0, t; }" : "=r"(a) : "l"(p));
  return a;
}
__device__ __forceinline__ void ldsm4(uint32_t& r0, uint32_t& r1, uint32_t& r2,
                                      uint32_t& r3, uint32_t addr) {
  asm volatile("ldmatrix.sync.aligned.m8n8.x4.shared.b16 {%0,%1,%2,%3}, [%4];"
               : "=r"(r0), "=r"(r1), "=r"(r2), "=r"(r3) : "r"(addr));
}
__device__ __forceinline__ void mma16816(float& c0, float& c1, float& c2, float& c3,
                                         uint32_t a0, uint32_t a1, uint32_t a2, uint32_t a3,
                                         uint32_t b0, uint32_t b1) {
  asm volatile("mma.sync.aligned.m16n8k16.row.col.f32.bf16.bf16.f32 "
               "{%0,%1,%2,%3}, {%4,%5,%6,%7}, {%8,%9}, {%0,%1,%2,%3};"
               : "+f"(c0), "+f"(c1), "+f"(c2), "+f"(c3)
               : "r"(a0), "r"(a1), "r"(a2), "r"(a3), "r"(b0), "r"(b1));
}
#define CP_ASYNC16(dst, src) \
  asm volatile("cp.async.cg.shared.global [%0], [%1], 16;" :: "r"(dst), "l"(src))
#define CP_COMMIT() asm volatile("cp.async.commit_group;")
#define CP_WAIT(n)  asm volatile("cp.async.wait_group %0;" :: "n"(n) : "memory")

// ===========================================================================
// prep: split fp32 row-major -> bf16 hi/lo row-major
// ===========================================================================
__device__ __forceinline__ void split_body(const float4* __restrict__ in,
                                           __nv_bfloat162* __restrict__ hi,
                                           __nv_bfloat162* __restrict__ lo, int i) {
  float4 v = in[i];
  __nv_bfloat16 hx = __float2bfloat16_rn(v.x);
  __nv_bfloat16 hy = __float2bfloat16_rn(v.y);
  __nv_bfloat16 hz = __float2bfloat16_rn(v.z);
  __nv_bfloat16 hw = __float2bfloat16_rn(v.w);
  hi[2*i+0] = __nv_bfloat162(hx, hy);
  hi[2*i+1] = __nv_bfloat162(hz, hw);
  lo[2*i+0] = __nv_bfloat162(__float2bfloat16_rn(v.x - __bfloat162float(hx)),
                             __float2bfloat16_rn(v.y - __bfloat162float(hy)));
  lo[2*i+1] = __nv_bfloat162(__float2bfloat16_rn(v.z - __bfloat162float(hz)),
                             __float2bfloat16_rn(v.w - __bfloat162float(hw)));
}

__global__ void __launch_bounds__(256)
split_rm(const float4* __restrict__ in, __nv_bfloat162* __restrict__ hi,
         __nv_bfloat162* __restrict__ lo, int n4) {
  int i = blockIdx.x*256 + threadIdx.x;
  if (i >= n4) return;
  split_body(in, hi, lo, i);
}

// fused split of the two 256x256 weights (one launch, 128 blocks)
__global__ void __launch_bounds__(256)
split_w2(const float4* __restrict__ w1, __nv_bfloat162* __restrict__ h1,
         __nv_bfloat162* __restrict__ l1,
         const float4* __restrict__ w2, __nv_bfloat162* __restrict__ h2,
         __nv_bfloat162* __restrict__ l2) {
  int b = blockIdx.x;
  if (b < 64) split_body(w1, h1, l1, b*256 + threadIdx.x);
  else        split_body(w2, h2, l2, (b-64)*256 + threadIdx.x);
}

// ===========================================================================
// Split-bf16 warp-MMA GEMM, chunk-major B loads + PASS-MAJOR mma order
// (acc reuse distance 16 MMAs to avoid accumulator RAW serialization).
// Block: 128 rows x 128 cols, 8 warps (4M x 2N), A hi|lo resident in smem.
// MODE 0: bias + fp32 store.  MODE 1: silu + group dot -> g_offaw.
// MODE 2: bias + fp16 store (value projection).
// ===========================================================================
template<int MODE, int NT>
__global__ void __launch_bounds__(256, 1)
gemm_mma(const uint4* __restrict__ Ah, const uint4* __restrict__ Al,
         const uint4* __restrict__ Bh, const uint4* __restrict__ Bl,
         const float* __restrict__ c0, const float* __restrict__ c1,
         void* __restrict__ OutV) {
  extern __shared__ char dsm[];
  const uint32_t as = s2u(dsm);            // A: 128 rows x 1024B = 131072
  const uint32_t bsb = as + 131072u;       // B: 3 x 32768 (hi 16KB | lo 16KB)
  const int tid = threadIdx.x;
  const int wid = tid >> 5, lane = tid & 31;
  const int mw = wid & 3, nw = wid >> 2;
  const int r0 = blockIdx.x * 128;
  const int N0 = blockIdx.y * NT * 128;

  // ---- load A (hi segs 0-3, lo segs 4-7 per 1KB row), swizzled ----
#pragma unroll
  for (int it = 0; it < 32; ++it) {
    int i = it*256 + tid;                  // 0..8191
    int r = i >> 6, u = i & 63;
    int half = u >> 5, uu = u & 31;
    int s = (half << 2) + (uu >> 3), c = uu & 7;
    const uint4* src = (half ? Al : Ah) + (size_t)(r0 + r)*32 + uu;
    uint32_t dst = as + (uint32_t)r*1024u + (uint32_t)s*128u + (uint32_t)((c ^ (r & 7))*16);
    CP_ASYNC16(dst, src);
  }
  CP_COMMIT();

  // lane-invariant pieces
  const int lA = mw*32 + (lane & 15);      // A row within tile
  const int jj = lane >> 4;                // 8-col group
  const int nB = nw*64 + (lane & 15);      // B row within tile
  const uint32_t pA = as + (uint32_t)lA*1024u;
  const int swA = lA & 7, swB = nB & 7;

  for (int nt = 0; nt < NT; ++nt) {
    float acc[2][8][4];
#pragma unroll
    for (int a = 0; a < 2; ++a)
#pragma unroll
      for (int b = 0; b < 8; ++b)
#pragma unroll
        for (int d = 0; d < 4; ++d) acc[a][b][d] = 0.f;

    const int nrow0 = N0 + nt*128;

    // prefetch k-chunk c4 (Bh 16KB + Bl 16KB) into buffer bi
    auto prefetchC4 = [&](int c4, int bi) {
#pragma unroll
      for (int it = 0; it < 8; ++it) {
        int i = it*256 + tid;              // 0..2047
        int n = i >> 4, u = i & 15;
        int sub = u >> 3, c = u & 7;       // sub: 0=hi, 1=lo
        const uint4* src = (sub ? Bl : Bh) + (size_t)(nrow0 + n)*32 + c4*8 + c;
        uint32_t dst = bsb + (uint32_t)bi*32768u + (uint32_t)sub*16384u
                     + (uint32_t)n*128u + (uint32_t)((c ^ (n & 7))*16);
        CP_ASYNC16(dst, src);
      }
      CP_COMMIT();
    };

    prefetchC4(0, 0);
    prefetchC4(1, 1);

#pragma unroll
    for (int c4 = 0; c4 < 4; ++c4) {
      if (c4 == 3) { CP_WAIT(0); } else { CP_WAIT(1); }
      __syncthreads();
      if (c4 + 2 < 4) prefetchC4(c4 + 2, (c4 + 2) % 3);

      const uint32_t bs  = bsb + (uint32_t)(c4 % 3)*32768u;
      const uint32_t aBh = pA + (uint32_t)c4*128u;
      const uint32_t aBl = pA + (uint32_t)(4 + c4)*128u;
#pragma unroll
      for (int ks = 0; ks < 4; ++ks) {
        const int cc = ks*2 + jj;
        const uint32_t csw = (uint32_t)((cc ^ swA)*16);
        uint32_t ah[2][4], al[2][4];
        ldsm4(ah[0][0], ah[0][1], ah[0][2], ah[0][3], aBh + csw);
        ldsm4(ah[1][0], ah[1][1], ah[1][2], ah[1][3], aBh + 16384u + csw);
        ldsm4(al[0][0], al[0][1], al[0][2], al[0][3], aBl + csw);
        ldsm4(al[1][0], al[1][1], al[1][2], al[1][3], aBl + 16384u + csw);
        const uint32_t bsw = (uint32_t)((cc ^ swB)*16);
        uint32_t bh[4][4], bl[4][4];
#pragma unroll
        for (int qt = 0; qt < 4; ++qt) {
          ldsm4(bh[qt][0], bh[qt][1], bh[qt][2], bh[qt][3],
                bs + (uint32_t)nB*128u + (uint32_t)qt*2048u + bsw);
          ldsm4(bl[qt][0], bl[qt][1], bl[qt][2], bl[qt][3],
                bs + 16384u + (uint32_t)nB*128u + (uint32_t)qt*2048u + bsw);
        }
        // pass-major: all 16 accumulators per term pass (RAW distance = 16)
#pragma unroll
        for (int qt = 0; qt < 4; ++qt)
#pragma unroll
          for (int mt = 0; mt < 2; ++mt) {
            mma16816(acc[mt][qt*2  ][0], acc[mt][qt*2  ][1], acc[mt][qt*2  ][2], acc[mt][qt*2  ][3],
                     ah[mt][0], ah[mt][1], ah[mt][2], ah[mt][3], bh[qt][0], bh[qt][2]);
            mma16816(acc[mt][qt*2+1][0], acc[mt][qt*2+1][1], acc[mt][qt*2+1][2], acc[mt][qt*2+1][3],
                     ah[mt][0], ah[mt][1], ah[mt][2], ah[mt][3], bh[qt][1], bh[qt][3]);
          }
#pragma unroll
        for (int qt = 0; qt < 4; ++qt)
#pragma unroll
          for (int mt = 0; mt < 2; ++mt) {
            mma16816(acc[mt][qt*2  ][0], acc[mt][qt*2  ][1], acc[mt][qt*2  ][2], acc[mt][qt*2  ][3],
                     al[mt][0], al[mt][1], al[mt][2], al[mt][3], bh[qt][0], bh[qt][2]);
            mma16816(acc[mt][qt*2+1][0], acc[mt][qt*2+1][1], acc[mt][qt*2+1][2], acc[mt][qt*2+1][3],
                     al[mt][0], al[mt][1], al[mt][2], al[mt][3], bh[qt][1], bh[qt][3]);
          }
#pragma unroll
        for (int qt = 0; qt < 4; ++qt)
#pragma unroll
          for (int mt = 0; mt < 2; ++mt) {
            mma16816(acc[mt][qt*2  ][0], acc[mt][qt*2  ][1], acc[mt][qt*2  ][2], acc[mt][qt*2  ][3],
                     ah[mt][0], ah[mt][1], ah[mt][2], ah[mt][3], bl[qt][0], bl[qt][2]);
            mma16816(acc[mt][qt*2+1][0], acc[mt][qt*2+1][1], acc[mt][qt*2+1][2], acc[mt][qt*2+1][3],
                     ah[mt][0], ah[mt][1], ah[mt][2], ah[mt][3], bl[qt][1], bl[qt][3]);
          }
      }
    }
    __syncthreads();   // protect buf0 from next nt's prefetch

    // ---- epilogue ----
    if (MODE == 0 || MODE == 2) {
#pragma unroll
      for (int mt = 0; mt < 2; ++mt)
#pragma unroll
        for (int h = 0; h < 2; ++h) {
          int row = r0 + mw*32 + mt*16 + (lane >> 2) + h*8;
#pragma unroll
          for (int j = 0; j < 8; ++j) {
            int col = nt*128 + nw*64 + j*8 + (lane & 3)*2;
            float ox = acc[mt][j][h*2+0] + c0[col];
            float oy = acc[mt][j][h*2+1] + c0[col+1];
            if (MODE == 0) {
              float2 o; o.x = ox; o.y = oy;
              *reinterpret_cast<float2*>((float*)OutV + (size_t)row*256 + col) = o;
            } else {
              __half2 o = __floats2half2_rn(ox, oy);
              *reinterpret_cast<__half2*>((__half*)OutV + (size_t)row*256 + col) = o;
            }
          }
        }
    } else {
      const float2* sw2 = reinterpret_cast<const float2*>(c0);
      float* Out = (float*)OutV;
#pragma unroll
      for (int grp = 0; grp < 2; ++grp) {
        int g = (N0 + nt*128 + nw*64 + grp*32) >> 5;
        float wx[4][2], wy[4][2], wl[4][2];
#pragma unroll
        for (int j = 0; j < 4; ++j) {
          int col = g*32 + j*8 + (lane & 3)*2;
          float2 q0 = __ldg(&sw2[col]), q1 = __ldg(&sw2[col+1]);
          wx[j][0] = q0.x; wy[j][0] = q0.y;
          wx[j][1] = q1.x; wy[j][1] = q1.y;
          wl[j][0] = __ldg(&c1[col]); wl[j][1] = __ldg(&c1[col+1]);
        }
#pragma unroll
        for (int mt = 0; mt < 2; ++mt)
#pragma unroll
          for (int h = 0; h < 2; ++h) {
            int row = r0 + mw*32 + mt*16 + (lane >> 2) + h*8;
            float sx = 0.f, sy = 0.f, sl = 0.f;
#pragma unroll
            for (int j = 0; j < 4; ++j) {
              float v0 = acc[mt][grp*4+j][h*2+0];
              float v1 = acc[mt][grp*4+j][h*2+1];
              v0 = v0 / (1.f + __expf(-v0));
              v1 = v1 / (1.f + __expf(-v1));
              sx = fmaf(v0, wx[j][0], sx); sx = fmaf(v1, wx[j][1], sx);
              sy = fmaf(v0, wy[j][0], sy); sy = fmaf(v1, wy[j][1], sy);
              sl = fmaf(v0, wl[j][0], sl); sl = fmaf(v1, wl[j][1], sl);
            }
            sx += __shfl_xor_sync(0xffffffffu, sx, 1);
            sy += __shfl_xor_sync(0xffffffffu, sy, 1);
            sl += __shfl_xor_sync(0xffffffffu, sl, 1);
            sx += __shfl_xor_sync(0xffffffffu, sx, 2);
            sy += __shfl_xor_sync(0xffffffffu, sy, 2);
            sl += __shfl_xor_sync(0xffffffffu, sl, 2);
            if ((lane & 3) == 0) {
              float* o = Out + ((size_t)g*MTOT + row)*3;
              o[0] = sx; o[1] = sy; o[2] = sl;
            }
          }
      }
    }
  }
}

// ===========================================================================
// Sampling: one warp per (b,q,head). fp16 value gathers.
// ===========================================================================
__global__ void __launch_bounds__(256)
sample_kernel(const float* __restrict__ ref, const float* __restrict__ sob,
              const float* __restrict__ attb) {
  __shared__ float s_lx[NH][16], s_ly[NH][16], s_aw[NH][16];
  const int bq   = blockIdx.x;
  const int b    = bq / LEN;
  const int h    = threadIdx.x >> 5;
  const int lane = threadIdx.x & 31;
  const int p    = lane & 15;
  const int l    = p >> 2;

  const float SZ[4] = {64.f, 32.f, 16.f, 8.f};
  int g = h*16 + p;
  size_t ob = ((size_t)g*MTOT + bq)*3;
  float rx = g_offaw[ob+0], ry = g_offaw[ob+1], rl = g_offaw[ob+2];
  float inv = 1.f / SZ[l];
  float lx = ref[(size_t)bq*8 + l*2 + 0] + (rx + sob[g*2+0]) * inv;
  float ly = ref[(size_t)bq*8 + l*2 + 1] + (ry + sob[g*2+1]) * inv;
  float logit = rl + attb[g];

  float mx = logit;
#pragma unroll
  for (int off = 8; off; off >>= 1)
    mx = fmaxf(mx, __shfl_xor_sync(0xffffffffu, mx, off, 16));
  float e = __expf(logit - mx);
  float ssum = e;
#pragma unroll
  for (int off = 8; off; off >>= 1)
    ssum += __shfl_xor_sync(0xffffffffu, ssum, off, 16);
  float aw = e / ssum;

  if (lane < 16) { s_lx[h][p] = lx; s_ly[h][p] = ly; s_aw[h][p] = aw; }
  __syncwarp(0xffffffffu);

  const int ST[4]  = {0, 4096, 5120, 5376};
  const int SZI[4] = {64, 32, 16, 8};
  float acc = 0.f;
  const __half* vbase = g_value + (size_t)b*LEN*DM + h*32 + lane;

#pragma unroll
  for (int pp = 0; pp < 16; ++pp) {
    int ll = pp >> 2;
    int S  = SZI[ll];
    float x = s_lx[h][pp]*(float)S - 0.5f;
    float y = s_ly[h][pp]*(float)S - 0.5f;
    float w = s_aw[h][pp];
    float fx = floorf(x), fy = floorf(y);
    int x0 = (int)fx, y0 = (int)fy;
    float wx = x - fx, wy = y - fy;
    const __half* vl = vbase + (size_t)ST[ll]*DM;
    float v00 = 0.f, v01 = 0.f, v10 = 0.f, v11 = 0.f;
    bool xa = (x0   >= 0) && (x0   < S);
    bool xb = (x0+1 >= 0) && (x0+1 < S);
    bool ya = (y0   >= 0) && (y0   < S);
    bool yb = (y0+1 >= 0) && (y0+1 < S);
    if (xa && ya) v00 = __half2float(vl[(size_t)(y0*S + x0  )*DM]);
    if (xb && ya) v01 = __half2float(vl[(size_t)(y0*S + x0+1)*DM]);
    if (xa && yb) v10 = __half2float(vl[(size_t)((y0+1)*S + x0  )*DM]);
    if (xb && yb) v11 = __half2float(vl[(size_t)((y0+1)*S + x0+1)*DM]);
    acc += w * ((v00*(1.f-wx) + v01*wx)*(1.f-wy) + (v10*(1.f-wx) + v11*wx)*wy);
  }
  __nv_bfloat16 hh = __float2bfloat16_rn(acc);
  __nv_bfloat16 ll16 = __float2bfloat16_rn(acc - __bfloat162float(hh));
  __nv_bfloat16* mh = reinterpret_cast<__nv_bfloat16*>(g_mh);
  __nv_bfloat16* ml = reinterpret_cast<__nv_bfloat16*>(g_ml);
  mh[(size_t)bq*256 + h*32 + lane] = hh;
  ml[(size_t)bq*256 + h*32 + lane] = ll16;
}

// ===========================================================================
extern "C" void kernel_launch(void* const* d_in, const int* in_sizes, int n_in,
                              void* d_out, int out_size) {
  (void)in_sizes; (void)n_in; (void)out_size;
  const float* query  = (const float*)d_in[0];
  const float* ref    = (const float*)d_in[1];
  const float* inputf = (const float*)d_in[2];
  const float* oeW    = (const float*)d_in[4];
  const float* sow    = (const float*)d_in[5];
  const float* sob    = (const float*)d_in[6];
  const float* attW   = (const float*)d_in[7];
  const float* attb   = (const float*)d_in[8];
  const float* valW   = (const float*)d_in[9];
  const float* valb   = (const float*)d_in[10];
  const float* outW   = (const float*)d_in[11];
  const float* outb   = (const float*)d_in[12];
  float* out = (float*)d_out;

  uint4 *qh,*ql,*ifh,*ifl,*mh,*ml,*wembh,*wembl,*vwh,*vwl,*owh,*owl;
  void *pval; float *pofa;
  cudaGetSymbolAddress((void**)&qh, g_qh);     cudaGetSymbolAddress((void**)&ql, g_ql);
  cudaGetSymbolAddress((void**)&ifh, g_ifh);   cudaGetSymbolAddress((void**)&ifl, g_ifl);
  cudaGetSymbolAddress((void**)&mh, g_mh);     cudaGetSymbolAddress((void**)&ml, g_ml);
  cudaGetSymbolAddress((void**)&wembh, g_wembh); cudaGetSymbolAddress((void**)&wembl, g_wembl);
  cudaGetSymbolAddress((void**)&vwh, g_vwh);   cudaGetSymbolAddress((void**)&vwl, g_vwl);
  cudaGetSymbolAddress((void**)&owh, g_owh);   cudaGetSymbolAddress((void**)&owl, g_owl);
  cudaGetSymbolAddress((void**)&pval, g_value);
  cudaGetSymbolAddress((void**)&pofa, g_offaw);

  const int dynsmem = 131072 + 3*32768;  // 224 KB
  cudaFuncSetAttribute(gemm_mma<0,2>, cudaFuncAttributeMaxDynamicSharedMemorySize, dynsmem);
  cudaFuncSetAttribute(gemm_mma<1,4>, cudaFuncAttributeMaxDynamicSharedMemorySize, dynsmem);
  cudaFuncSetAttribute(gemm_mma<2,2>, cudaFuncAttributeMaxDynamicSharedMemorySize, dynsmem);

  const int n4 = MTOT*64;
  // launch order: offset GEMM at our 0-based index 3 (where ncu lands)
  split_rm<<<n4/256, 256>>>(reinterpret_cast<const float4*>(query),
                            reinterpret_cast<__nv_bfloat162*>(qh),
                            reinterpret_cast<__nv_bfloat162*>(ql), n4);       // 0
  split_rm<<<1024, 256>>>(reinterpret_cast<const float4*>(oeW),
                          reinterpret_cast<__nv_bfloat162*>(wembh),
                          reinterpret_cast<__nv_bfloat162*>(wembl), 4096*64); // 1
  split_rm<<<n4/256, 256>>>(reinterpret_cast<const float4*>(inputf),
                            reinterpret_cast<__nv_bfloat162*>(ifh),
                            reinterpret_cast<__nv_bfloat162*>(ifl), n4);      // 2
  gemm_mma<1,4><<<dim3(MTOT/128,8), 256, dynsmem>>>(qh, ql, wembh, wembl,
                                                    sow, attW, pofa);         // 3
  split_w2<<<128, 256>>>(reinterpret_cast<const float4*>(valW),
                         reinterpret_cast<__nv_bfloat162*>(vwh),
                         reinterpret_cast<__nv_bfloat162*>(vwl),
                         reinterpret_cast<const float4*>(outW),
                         reinterpret_cast<__nv_bfloat162*>(owh),
                         reinterpret_cast<__nv_bfloat162*>(owl));             // 4
  gemm_mma<2,2><<<dim3(MTOT/128,1), 256, dynsmem>>>(ifh, ifl, vwh, vwl,
                                                    valb, nullptr, pval);     // 5
  sample_kernel<<<MTOT, 256>>>(ref, sob, attb);                               // 6
  gemm_mma<0,2><<<dim3(MTOT/128,1), 256, dynsmem>>>(mh, ml, owh, owl,
                                                    outb, nullptr, out);      // 7
}

// round 9
// speedup vs baseline: 2.8053x; 1.0746x over previous
#include <cuda_runtime.h>
#include <cuda_bf16.h>
#include <cuda_fp16.h>
#include <math.h>
#include <stdint.h>

#define NB   4
#define LEN  5440
#define MTOT (NB*LEN)      // 21760
#define DM   256
#define NH   8
#define NG   128

// ===========================================================================
// Scratch (allocation-free __device__ globals)
// ===========================================================================
__device__ uint4 g_qh[MTOT*32],  g_ql[MTOT*32];      // query split (row-major bf16)
__device__ uint4 g_ifh[MTOT*32], g_ifl[MTOT*32];     // input_flatten split
__device__ uint4 g_mh[MTOT*32],  g_ml[MTOT*32];      // mix (sample output) split
__device__ uint4 g_wembh[4096*32], g_wembl[4096*32]; // offset-embed W split
__device__ uint4 g_vwh[256*32],   g_vwl[256*32];     // value W split
__device__ uint4 g_owh[256*32],   g_owl[256*32];     // out W split
__device__ __half g_value[MTOT*DM];                  // value projection (fp16)
__device__ float g_offaw[(size_t)NG*MTOT*3];         // [group][row][3]

// ===========================================================================
__device__ __forceinline__ uint32_t s2u(const void* p) {
  uint32_t a;
  asm("{ .reg .u64 t; cvta.to.shared.u64 t, %1; cvt.u32.u64 %0, t; }" : "=r"(a) : "l"(p));
  return a;
}
__device__ __forceinline__ void ldsm4(uint32_t& r0, uint32_t& r1, uint32_t& r2,
                                      uint32_t& r3, uint32_t addr) {
  asm volatile("ldmatrix.sync.aligned.m8n8.x4.shared.b16 {%0,%1,%2,%3}, [%4];"
               : "=r"(r0), "=r"(r1), "=r"(r2), "=r"(r3) : "r"(addr));
}
__device__ __forceinline__ void mma16816(float& c0, float& c1, float& c2, float& c3,
                                         uint32_t a0, uint32_t a1, uint32_t a2, uint32_t a3,
                                         uint32_t b0, uint32_t b1) {
  asm volatile("mma.sync.aligned.m16n8k16.row.col.f32.bf16.bf16.f32 "
               "{%0,%1,%2,%3}, {%4,%5,%6,%7}, {%8,%9}, {%0,%1,%2,%3};"
               : "+f"(c0), "+f"(c1), "+f"(c2), "+f"(c3)
               : "r"(a0), "r"(a1), "r"(a2), "r"(a3), "r"(b0), "r"(b1));
}
#define CP_ASYNC16(dst, src) \
  asm volatile("cp.async.cg.shared.global [%0], [%1], 16;" :: "r"(dst), "l"(src))
#define CP_COMMIT() asm volatile("cp.async.commit_group;")
#define CP_WAIT(n)  asm volatile("cp.async.wait_group %0;" :: "n"(n) : "memory")

// ===========================================================================
// prep: split fp32 row-major -> bf16 hi/lo row-major
// ===========================================================================
__device__ __forceinline__ void split_body(const float4* __restrict__ in,
                                           __nv_bfloat162* __restrict__ hi,
                                           __nv_bfloat162* __restrict__ lo, int i) {
  float4 v = in[i];
  __nv_bfloat16 hx = __float2bfloat16_rn(v.x);
  __nv_bfloat16 hy = __float2bfloat16_rn(v.y);
  __nv_bfloat16 hz = __float2bfloat16_rn(v.z);
  __nv_bfloat16 hw = __float2bfloat16_rn(v.w);
  hi[2*i+0] = __nv_bfloat162(hx, hy);
  hi[2*i+1] = __nv_bfloat162(hz, hw);
  lo[2*i+0] = __nv_bfloat162(__float2bfloat16_rn(v.x - __bfloat162float(hx)),
                             __float2bfloat16_rn(v.y - __bfloat162float(hy)));
  lo[2*i+1] = __nv_bfloat162(__float2bfloat16_rn(v.z - __bfloat162float(hz)),
                             __float2bfloat16_rn(v.w - __bfloat162float(hw)));
}

__global__ void __launch_bounds__(256)
split_rm(const float4* __restrict__ in, __nv_bfloat162* __restrict__ hi,
         __nv_bfloat162* __restrict__ lo, int n4) {
  int i = blockIdx.x*256 + threadIdx.x;
  if (i >= n4) return;
  split_body(in, hi, lo, i);
}

// fused split of the two 256x256 weights (one launch, 128 blocks)
__global__ void __launch_bounds__(256)
split_w2(const float4* __restrict__ w1, __nv_bfloat162* __restrict__ h1,
         __nv_bfloat162* __restrict__ l1,
         const float4* __restrict__ w2, __nv_bfloat162* __restrict__ h2,
         __nv_bfloat162* __restrict__ l2) {
  int b = blockIdx.x;
  if (b < 64) split_body(w1, h1, l1, b*256 + threadIdx.x);
  else        split_body(w2, h2, l2, (b-64)*256 + threadIdx.x);
}

// ===========================================================================
// Split-bf16 warp-MMA GEMM. 512 threads, 16 warps (4M x 4N), warp tile 32x32:
// halves per-warp MMA/LDSM chains and doubles warps/SMSP for latency hiding
// (R8 ncu: tensor=47.6% at 8 warps => occupancy-starved).
// A hi|lo resident in smem; B double(triple)-buffered 32KB chunk pairs.
// MODE 0: bias + fp32 store.  MODE 1: silu + group dot -> g_offaw.
// MODE 2: bias + fp16 store (value projection).
// ===========================================================================
template<int MODE, int NT>
__global__ void __launch_bounds__(512, 1)
gemm_mma(const uint4* __restrict__ Ah, const uint4* __restrict__ Al,
         const uint4* __restrict__ Bh, const uint4* __restrict__ Bl,
         const float* __restrict__ c0, const float* __restrict__ c1,
         void* __restrict__ OutV) {
  extern __shared__ char dsm[];
  const uint32_t as = s2u(dsm);            // A: 128 rows x 1024B = 131072
  const uint32_t bsb = as + 131072u;       // B: 3 x 32768 (hi 16KB | lo 16KB)
  const int tid = threadIdx.x;
  const int wid = tid >> 5, lane = tid & 31;
  const int mw = wid & 3, nw = wid >> 2;   // 4M x 4N warps
  const int r0 = blockIdx.x * 128;
  const int N0 = blockIdx.y * NT * 128;

  // ---- load A (hi segs 0-3, lo segs 4-7 per 1KB row), swizzled ----
#pragma unroll
  for (int it = 0; it < 16; ++it) {
    int i = it*512 + tid;                  // 0..8191
    int r = i >> 6, u = i & 63;
    int half = u >> 5, uu = u & 31;
    int s = (half << 2) + (uu >> 3), c = uu & 7;
    const uint4* src = (half ? Al : Ah) + (size_t)(r0 + r)*32 + uu;
    uint32_t dst = as + (uint32_t)r*1024u + (uint32_t)s*128u + (uint32_t)((c ^ (r & 7))*16);
    CP_ASYNC16(dst, src);
  }
  CP_COMMIT();

  // lane-invariant pieces
  const int lA = mw*32 + (lane & 15);      // A row within tile
  const int jj = lane >> 4;                // 8-col group
  const int nB = nw*32 + (lane & 15);      // B row within tile (warp: 32 cols)
  const uint32_t pA = as + (uint32_t)lA*1024u;
  const int swA = lA & 7, swB = nB & 7;

  for (int nt = 0; nt < NT; ++nt) {
    float acc[2][4][4];
#pragma unroll
    for (int a = 0; a < 2; ++a)
#pragma unroll
      for (int b = 0; b < 4; ++b)
#pragma unroll
        for (int d = 0; d < 4; ++d) acc[a][b][d] = 0.f;

    const int nrow0 = N0 + nt*128;

    // prefetch k-chunk c4 (Bh 16KB + Bl 16KB) into buffer bi
    auto prefetchC4 = [&](int c4, int bi) {
#pragma unroll
      for (int it = 0; it < 4; ++it) {
        int i = it*512 + tid;              // 0..2047
        int n = i >> 4, u = i & 15;
        int sub = u >> 3, c = u & 7;       // sub: 0=hi, 1=lo
        const uint4* src = (sub ? Bl : Bh) + (size_t)(nrow0 + n)*32 + c4*8 + c;
        uint32_t dst = bsb + (uint32_t)bi*32768u + (uint32_t)sub*16384u
                     + (uint32_t)n*128u + (uint32_t)((c ^ (n & 7))*16);
        CP_ASYNC16(dst, src);
      }
      CP_COMMIT();
    };

    prefetchC4(0, 0);
    prefetchC4(1, 1);

#pragma unroll
    for (int c4 = 0; c4 < 4; ++c4) {
      if (c4 == 3) { CP_WAIT(0); } else { CP_WAIT(1); }
      __syncthreads();
      if (c4 + 2 < 4) prefetchC4(c4 + 2, (c4 + 2) % 3);

      const uint32_t bs  = bsb + (uint32_t)(c4 % 3)*32768u;
      const uint32_t aBh = pA + (uint32_t)c4*128u;
      const uint32_t aBl = pA + (uint32_t)(4 + c4)*128u;
#pragma unroll
      for (int ks = 0; ks < 4; ++ks) {
        const int cc = ks*2 + jj;
        const uint32_t csw = (uint32_t)((cc ^ swA)*16);
        uint32_t ah[2][4], al[2][4];
        ldsm4(ah[0][0], ah[0][1], ah[0][2], ah[0][3], aBh + csw);
        ldsm4(ah[1][0], ah[1][1], ah[1][2], ah[1][3], aBh + 16384u + csw);
        ldsm4(al[0][0], al[0][1], al[0][2], al[0][3], aBl + csw);
        ldsm4(al[1][0], al[1][1], al[1][2], al[1][3], aBl + 16384u + csw);
        const uint32_t bsw = (uint32_t)((cc ^ swB)*16);
        uint32_t bh[2][4], bl[2][4];
#pragma unroll
        for (int qt = 0; qt < 2; ++qt) {
          ldsm4(bh[qt][0], bh[qt][1], bh[qt][2], bh[qt][3],
                bs + (uint32_t)nB*128u + (uint32_t)qt*2048u + bsw);
          ldsm4(bl[qt][0], bl[qt][1], bl[qt][2], bl[qt][3],
                bs + 16384u + (uint32_t)nB*128u + (uint32_t)qt*2048u + bsw);
        }
        // pass-major (acc RAW distance = 8)
#pragma unroll
        for (int qt = 0; qt < 2; ++qt)
#pragma unroll
          for (int mt = 0; mt < 2; ++mt) {
            mma16816(acc[mt][qt*2  ][0], acc[mt][qt*2  ][1], acc[mt][qt*2  ][2], acc[mt][qt*2  ][3],
                     ah[mt][0], ah[mt][1], ah[mt][2], ah[mt][3], bh[qt][0], bh[qt][2]);
            mma16816(acc[mt][qt*2+1][0], acc[mt][qt*2+1][1], acc[mt][qt*2+1][2], acc[mt][qt*2+1][3],
                     ah[mt][0], ah[mt][1], ah[mt][2], ah[mt][3], bh[qt][1], bh[qt][3]);
          }
#pragma unroll
        for (int qt = 0; qt < 2; ++qt)
#pragma unroll
          for (int mt = 0; mt < 2; ++mt) {
            mma16816(acc[mt][qt*2  ][0], acc[mt][qt*2  ][1], acc[mt][qt*2  ][2], acc[mt][qt*2  ][3],
                     al[mt][0], al[mt][1], al[mt][2], al[mt][3], bh[qt][0], bh[qt][2]);
            mma16816(acc[mt][qt*2+1][0], acc[mt][qt*2+1][1], acc[mt][qt*2+1][2], acc[mt][qt*2+1][3],
                     al[mt][0], al[mt][1], al[mt][2], al[mt][3], bh[qt][1], bh[qt][3]);
          }
#pragma unroll
        for (int qt = 0; qt < 2; ++qt)
#pragma unroll
          for (int mt = 0; mt < 2; ++mt) {
            mma16816(acc[mt][qt*2  ][0], acc[mt][qt*2  ][1], acc[mt][qt*2  ][2], acc[mt][qt*2  ][3],
                     ah[mt][0], ah[mt][1], ah[mt][2], ah[mt][3], bl[qt][0], bl[qt][2]);
            mma16816(acc[mt][qt*2+1][0], acc[mt][qt*2+1][1], acc[mt][qt*2+1][2], acc[mt][qt*2+1][3],
                     ah[mt][0], ah[mt][1], ah[mt][2], ah[mt][3], bl[qt][1], bl[qt][3]);
          }
      }
    }
    __syncthreads();   // protect buf0 from next nt's prefetch

    // ---- epilogue ----
    if (MODE == 0 || MODE == 2) {
#pragma unroll
      for (int mt = 0; mt < 2; ++mt)
#pragma unroll
        for (int h = 0; h < 2; ++h) {
          int row = r0 + mw*32 + mt*16 + (lane >> 2) + h*8;
#pragma unroll
          for (int j = 0; j < 4; ++j) {
            int col = nt*128 + nw*32 + j*8 + (lane & 3)*2;
            float ox = acc[mt][j][h*2+0] + c0[col];
            float oy = acc[mt][j][h*2+1] + c0[col+1];
            if (MODE == 0) {
              float2 o; o.x = ox; o.y = oy;
              *reinterpret_cast<float2*>((float*)OutV + (size_t)row*256 + col) = o;
            } else {
              __half2 o = __floats2half2_rn(ox, oy);
              *reinterpret_cast<__half2*>((__half*)OutV + (size_t)row*256 + col) = o;
            }
          }
        }
    } else {
      const float2* sw2 = reinterpret_cast<const float2*>(c0);
      float* Out = (float*)OutV;
      int g = (N0 + nt*128 + nw*32) >> 5;  // one 32-col group per warp
      float wx[4][2], wy[4][2], wl[4][2];
#pragma unroll
      for (int j = 0; j < 4; ++j) {
        int col = g*32 + j*8 + (lane & 3)*2;
        float2 q0 = __ldg(&sw2[col]), q1 = __ldg(&sw2[col+1]);
        wx[j][0] = q0.x; wy[j][0] = q0.y;
        wx[j][1] = q1.x; wy[j][1] = q1.y;
        wl[j][0] = __ldg(&c1[col]); wl[j][1] = __ldg(&c1[col+1]);
      }
#pragma unroll
      for (int mt = 0; mt < 2; ++mt)
#pragma unroll
        for (int h = 0; h < 2; ++h) {
          int row = r0 + mw*32 + mt*16 + (lane >> 2) + h*8;
          float sx = 0.f, sy = 0.f, sl = 0.f;
#pragma unroll
          for (int j = 0; j < 4; ++j) {
            float v0 = acc[mt][j][h*2+0];
            float v1 = acc[mt][j][h*2+1];
            v0 = v0 / (1.f + __expf(-v0));
            v1 = v1 / (1.f + __expf(-v1));
            sx = fmaf(v0, wx[j][0], sx); sx = fmaf(v1, wx[j][1], sx);
            sy = fmaf(v0, wy[j][0], sy); sy = fmaf(v1, wy[j][1], sy);
            sl = fmaf(v0, wl[j][0], sl); sl = fmaf(v1, wl[j][1], sl);
          }
          sx += __shfl_xor_sync(0xffffffffu, sx, 1);
          sy += __shfl_xor_sync(0xffffffffu, sy, 1);
          sl += __shfl_xor_sync(0xffffffffu, sl, 1);
          sx += __shfl_xor_sync(0xffffffffu, sx, 2);
          sy += __shfl_xor_sync(0xffffffffu, sy, 2);
          sl += __shfl_xor_sync(0xffffffffu, sl, 2);
          if ((lane & 3) == 0) {
            float* o = Out + ((size_t)g*MTOT + row)*3;
            o[0] = sx; o[1] = sy; o[2] = sl;
          }
        }
    }
  }
}

// ===========================================================================
// Sampling: one warp per (b,q,head). fp16 value gathers.
// ===========================================================================
__global__ void __launch_bounds__(256)
sample_kernel(const float* __restrict__ ref, const float* __restrict__ sob,
              const float* __restrict__ attb) {
  __shared__ float s_lx[NH][16], s_ly[NH][16], s_aw[NH][16];
  const int bq   = blockIdx.x;
  const int b    = bq / LEN;
  const int h    = threadIdx.x >> 5;
  const int lane = threadIdx.x & 31;
  const int p    = lane & 15;
  const int l    = p >> 2;

  const float SZ[4] = {64.f, 32.f, 16.f, 8.f};
  int g = h*16 + p;
  size_t ob = ((size_t)g*MTOT + bq)*3;
  float rx = g_offaw[ob+0], ry = g_offaw[ob+1], rl = g_offaw[ob+2];
  float inv = 1.f / SZ[l];
  float lx = ref[(size_t)bq*8 + l*2 + 0] + (rx + sob[g*2+0]) * inv;
  float ly = ref[(size_t)bq*8 + l*2 + 1] + (ry + sob[g*2+1]) * inv;
  float logit = rl + attb[g];

  float mx = logit;
#pragma unroll
  for (int off = 8; off; off >>= 1)
    mx = fmaxf(mx, __shfl_xor_sync(0xffffffffu, mx, off, 16));
  float e = __expf(logit - mx);
  float ssum = e;
#pragma unroll
  for (int off = 8; off; off >>= 1)
    ssum += __shfl_xor_sync(0xffffffffu, ssum, off, 16);
  float aw = e / ssum;

  if (lane < 16) { s_lx[h][p] = lx; s_ly[h][p] = ly; s_aw[h][p] = aw; }
  __syncwarp(0xffffffffu);

  const int ST[4]  = {0, 4096, 5120, 5376};
  const int SZI[4] = {64, 32, 16, 8};
  float acc = 0.f;
  const __half* vbase = g_value + (size_t)b*LEN*DM + h*32 + lane;

#pragma unroll
  for (int pp = 0; pp < 16; ++pp) {
    int ll = pp >> 2;
    int S  = SZI[ll];
    float x = s_lx[h][pp]*(float)S - 0.5f;
    float y = s_ly[h][pp]*(float)S - 0.5f;
    float w = s_aw[h][pp];
    float fx = floorf(x), fy = floorf(y);
    int x0 = (int)fx, y0 = (int)fy;
    float wx = x - fx, wy = y - fy;
    const __half* vl = vbase + (size_t)ST[ll]*DM;
    float v00 = 0.f, v01 = 0.f, v10 = 0.f, v11 = 0.f;
    bool xa = (x0   >= 0) && (x0   < S);
    bool xb = (x0+1 >= 0) && (x0+1 < S);
    bool ya = (y0   >= 0) && (y0   < S);
    bool yb = (y0+1 >= 0) && (y0+1 < S);
    if (xa && ya) v00 = __half2float(vl[(size_t)(y0*S + x0  )*DM]);
    if (xb && ya) v01 = __half2float(vl[(size_t)(y0*S + x0+1)*DM]);
    if (xa && yb) v10 = __half2float(vl[(size_t)((y0+1)*S + x0  )*DM]);
    if (xb && yb) v11 = __half2float(vl[(size_t)((y0+1)*S + x0+1)*DM]);
    acc += w * ((v00*(1.f-wx) + v01*wx)*(1.f-wy) + (v10*(1.f-wx) + v11*wx)*wy);
  }
  __nv_bfloat16 hh = __float2bfloat16_rn(acc);
  __nv_bfloat16 ll16 = __float2bfloat16_rn(acc - __bfloat162float(hh));
  __nv_bfloat16* mh = reinterpret_cast<__nv_bfloat16*>(g_mh);
  __nv_bfloat16* ml = reinterpret_cast<__nv_bfloat16*>(g_ml);
  mh[(size_t)bq*256 + h*32 + lane] = hh;
  ml[(size_t)bq*256 + h*32 + lane] = ll16;
}

// ===========================================================================
extern "C" void kernel_launch(void* const* d_in, const int* in_sizes, int n_in,
                              void* d_out, int out_size) {
  (void)in_sizes; (void)n_in; (void)out_size;
  const float* query  = (const float*)d_in[0];
  const float* ref    = (const float*)d_in[1];
  const float* inputf = (const float*)d_in[2];
  const float* oeW    = (const float*)d_in[4];
  const float* sow    = (const float*)d_in[5];
  const float* sob    = (const float*)d_in[6];
  const float* attW   = (const float*)d_in[7];
  const float* attb   = (const float*)d_in[8];
  const float* valW   = (const float*)d_in[9];
  const float* valb   = (const float*)d_in[10];
  const float* outW   = (const float*)d_in[11];
  const float* outb   = (const float*)d_in[12];
  float* out = (float*)d_out;

  uint4 *qh,*ql,*ifh,*ifl,*mh,*ml,*wembh,*wembl,*vwh,*vwl,*owh,*owl;
  void *pval; float *pofa;
  cudaGetSymbolAddress((void**)&qh, g_qh);     cudaGetSymbolAddress((void**)&ql, g_ql);
  cudaGetSymbolAddress((void**)&ifh, g_ifh);   cudaGetSymbolAddress((void**)&ifl, g_ifl);
  cudaGetSymbolAddress((void**)&mh, g_mh);     cudaGetSymbolAddress((void**)&ml, g_ml);
  cudaGetSymbolAddress((void**)&wembh, g_wembh); cudaGetSymbolAddress((void**)&wembl, g_wembl);
  cudaGetSymbolAddress((void**)&vwh, g_vwh);   cudaGetSymbolAddress((void**)&vwl, g_vwl);
  cudaGetSymbolAddress((void**)&owh, g_owh);   cudaGetSymbolAddress((void**)&owl, g_owl);
  cudaGetSymbolAddress((void**)&pval, g_value);
  cudaGetSymbolAddress((void**)&pofa, g_offaw);

  const int dynsmem = 131072 + 3*32768;  // 224 KB
  cudaFuncSetAttribute(gemm_mma<0,2>, cudaFuncAttributeMaxDynamicSharedMemorySize, dynsmem);
  cudaFuncSetAttribute(gemm_mma<1,4>, cudaFuncAttributeMaxDynamicSharedMemorySize, dynsmem);
  cudaFuncSetAttribute(gemm_mma<2,2>, cudaFuncAttributeMaxDynamicSharedMemorySize, dynsmem);

  const int n4 = MTOT*64;
  // launch order: offset GEMM at our 0-based index 3 (where ncu lands)
  split_rm<<<n4/256, 256>>>(reinterpret_cast<const float4*>(query),
                            reinterpret_cast<__nv_bfloat162*>(qh),
                            reinterpret_cast<__nv_bfloat162*>(ql), n4);       // 0
  split_rm<<<1024, 256>>>(reinterpret_cast<const float4*>(oeW),
                          reinterpret_cast<__nv_bfloat162*>(wembh),
                          reinterpret_cast<__nv_bfloat162*>(wembl), 4096*64); // 1
  split_rm<<<n4/256, 256>>>(reinterpret_cast<const float4*>(inputf),
                            reinterpret_cast<__nv_bfloat162*>(ifh),
                            reinterpret_cast<__nv_bfloat162*>(ifl), n4);      // 2
  gemm_mma<1,4><<<dim3(MTOT/128,8), 512, dynsmem>>>(qh, ql, wembh, wembl,
                                                    sow, attW, pofa);         // 3
  split_w2<<<128, 256>>>(reinterpret_cast<const float4*>(valW),
                         reinterpret_cast<__nv_bfloat162*>(vwh),
                         reinterpret_cast<__nv_bfloat162*>(vwl),
                         reinterpret_cast<const float4*>(outW),
                         reinterpret_cast<__nv_bfloat162*>(owh),
                         reinterpret_cast<__nv_bfloat162*>(owl));             // 4
  gemm_mma<2,2><<<dim3(MTOT/128,1), 512, dynsmem>>>(ifh, ifl, vwh, vwl,
                                                    valb, nullptr, pval);     // 5
  sample_kernel<<<MTOT, 256>>>(ref, sob, attb);                               // 6
  gemm_mma<0,2><<<dim3(MTOT/128,1), 512, dynsmem>>>(mh, ml, owh, owl,
                                                    outb, nullptr, out);      // 7
}

// round 10
// speedup vs baseline: 2.8997x; 1.0336x over previous
#include <cuda_runtime.h>
#include <cuda_bf16.h>
#include <cuda_fp16.h>
#include <math.h>
#include <stdint.h>

#define NB   4
#define LEN  5440
#define MTOT (NB*LEN)      // 21760
#define DM   256
#define NH   8
#define NG   128

// ===========================================================================
// Scratch (allocation-free __device__ globals)
// ===========================================================================
__device__ uint4 g_qh[MTOT*32],  g_ql[MTOT*32];      // query split (row-major bf16)
__device__ uint4 g_ifh[MTOT*32], g_ifl[MTOT*32];     // input_flatten split
__device__ uint4 g_mh[MTOT*32],  g_ml[MTOT*32];      // mix (sample output) split
__device__ uint4 g_wembh[4096*32], g_wembl[4096*32]; // offset-embed W split
__device__ uint4 g_vwh[256*32],   g_vwl[256*32];     // value W split
__device__ uint4 g_owh[256*32],   g_owl[256*32];     // out W split
__device__ __half g_value[MTOT*DM];                  // value projection (fp16)
__device__ float g_offaw[(size_t)NG*MTOT*3];         // [group][row][3]

// ===========================================================================
__device__ __forceinline__ uint32_t s2u(const void* p) {
  uint32_t a;
  asm("{ .reg .u64 t; cvta.to.shared.u64 t, %1; cvt.u32.u64 %0, t; }" : "=r"(a) : "l"(p));
  return a;
}
__device__ __forceinline__ void ldsm4(uint32_t& r0, uint32_t& r1, uint32_t& r2,
                                      uint32_t& r3, uint32_t addr) {
  asm volatile("ldmatrix.sync.aligned.m8n8.x4.shared.b16 {%0,%1,%2,%3}, [%4];"
               : "=r"(r0), "=r"(r1), "=r"(r2), "=r"(r3) : "r"(addr));
}
__device__ __forceinline__ void mma16816(float& c0, float& c1, float& c2, float& c3,
                                         uint32_t a0, uint32_t a1, uint32_t a2, uint32_t a3,
                                         uint32_t b0, uint32_t b1) {
  asm volatile("mma.sync.aligned.m16n8k16.row.col.f32.bf16.bf16.f32 "
               "{%0,%1,%2,%3}, {%4,%5,%6,%7}, {%8,%9}, {%0,%1,%2,%3};"
               : "+f"(c0), "+f"(c1), "+f"(c2), "+f"(c3)
               : "r"(a0), "r"(a1), "r"(a2), "r"(a3), "r"(b0), "r"(b1));
}
#define CP_ASYNC16(dst, src) \
  asm volatile("cp.async.cg.shared.global [%0], [%1], 16;" :: "r"(dst), "l"(src))
#define CP_COMMIT() asm volatile("cp.async.commit_group;")
#define CP_WAIT(n)  asm volatile("cp.async.wait_group %0;" :: "n"(n) : "memory")

// ===========================================================================
// prep: split fp32 row-major -> bf16 hi/lo row-major
// ===========================================================================
__device__ __forceinline__ void split_body(const float4* __restrict__ in,
                                           __nv_bfloat162* __restrict__ hi,
                                           __nv_bfloat162* __restrict__ lo, int i) {
  float4 v = in[i];
  __nv_bfloat16 hx = __float2bfloat16_rn(v.x);
  __nv_bfloat16 hy = __float2bfloat16_rn(v.y);
  __nv_bfloat16 hz = __float2bfloat16_rn(v.z);
  __nv_bfloat16 hw = __float2bfloat16_rn(v.w);
  hi[2*i+0] = __nv_bfloat162(hx, hy);
  hi[2*i+1] = __nv_bfloat162(hz, hw);
  lo[2*i+0] = __nv_bfloat162(__float2bfloat16_rn(v.x - __bfloat162float(hx)),
                             __float2bfloat16_rn(v.y - __bfloat162float(hy)));
  lo[2*i+1] = __nv_bfloat162(__float2bfloat16_rn(v.z - __bfloat162float(hz)),
                             __float2bfloat16_rn(v.w - __bfloat162float(hw)));
}

__global__ void __launch_bounds__(256)
split_rm(const float4* __restrict__ in, __nv_bfloat162* __restrict__ hi,
         __nv_bfloat162* __restrict__ lo, int n4) {
  int i = blockIdx.x*256 + threadIdx.x;
  if (i >= n4) return;
  split_body(in, hi, lo, i);
}

// fused split: input_flatten (blocks 0..5439) + valW (5440..5503) + outW (5504..5567)
__global__ void __launch_bounds__(256)
split_ifw(const float4* __restrict__ inf, __nv_bfloat162* __restrict__ ifh,
          __nv_bfloat162* __restrict__ ifl,
          const float4* __restrict__ w1, __nv_bfloat162* __restrict__ h1,
          __nv_bfloat162* __restrict__ l1,
          const float4* __restrict__ w2, __nv_bfloat162* __restrict__ h2,
          __nv_bfloat162* __restrict__ l2) {
  int b = blockIdx.x;
  if (b < 5440)      split_body(inf, ifh, ifl, b*256 + threadIdx.x);
  else if (b < 5504) split_body(w1, h1, l1, (b-5440)*256 + threadIdx.x);
  else               split_body(w2, h2, l2, (b-5504)*256 + threadIdx.x);
}

// ===========================================================================
// Split-bf16 warp-MMA GEMM body. 512 threads, 16 warps (4M x 4N), 32x32 warp
// tile. A hi|lo resident in smem; B triple-buffered 32KB chunk pairs.
// MODE 0: bias + fp32 store.  MODE 1: silu + group dot -> g_offaw.
// MODE 2: bias + fp16 store (value projection).
// ===========================================================================
template<int MODE, int NT>
__device__ __forceinline__ void gemm_body(
    const uint4* __restrict__ Ah, const uint4* __restrict__ Al,
    const uint4* __restrict__ Bh, const uint4* __restrict__ Bl,
    const float* __restrict__ c0, const float* __restrict__ c1,
    void* __restrict__ OutV, int r0, int N0) {
  extern __shared__ char dsm[];
  const uint32_t as = s2u(dsm);            // A: 128 rows x 1024B = 131072
  const uint32_t bsb = as + 131072u;       // B: 3 x 32768 (hi 16KB | lo 16KB)
  const int tid = threadIdx.x;
  const int wid = tid >> 5, lane = tid & 31;
  const int mw = wid & 3, nw = wid >> 2;   // 4M x 4N warps

  // ---- load A (hi segs 0-3, lo segs 4-7 per 1KB row), swizzled ----
#pragma unroll
  for (int it = 0; it < 16; ++it) {
    int i = it*512 + tid;                  // 0..8191
    int r = i >> 6, u = i & 63;
    int half = u >> 5, uu = u & 31;
    int s = (half << 2) + (uu >> 3), c = uu & 7;
    const uint4* src = (half ? Al : Ah) + (size_t)(r0 + r)*32 + uu;
    uint32_t dst = as + (uint32_t)r*1024u + (uint32_t)s*128u + (uint32_t)((c ^ (r & 7))*16);
    CP_ASYNC16(dst, src);
  }
  CP_COMMIT();

  const int lA = mw*32 + (lane & 15);
  const int jj = lane >> 4;
  const int nB = nw*32 + (lane & 15);
  const uint32_t pA = as + (uint32_t)lA*1024u;
  const int swA = lA & 7, swB = nB & 7;

  for (int nt = 0; nt < NT; ++nt) {
    float acc[2][4][4];
#pragma unroll
    for (int a = 0; a < 2; ++a)
#pragma unroll
      for (int b = 0; b < 4; ++b)
#pragma unroll
        for (int d = 0; d < 4; ++d) acc[a][b][d] = 0.f;

    const int nrow0 = N0 + nt*128;

    auto prefetchC4 = [&](int c4, int bi) {
#pragma unroll
      for (int it = 0; it < 4; ++it) {
        int i = it*512 + tid;              // 0..2047
        int n = i >> 4, u = i & 15;
        int sub = u >> 3, c = u & 7;
        const uint4* src = (sub ? Bl : Bh) + (size_t)(nrow0 + n)*32 + c4*8 + c;
        uint32_t dst = bsb + (uint32_t)bi*32768u + (uint32_t)sub*16384u
                     + (uint32_t)n*128u + (uint32_t)((c ^ (n & 7))*16);
        CP_ASYNC16(dst, src);
      }
      CP_COMMIT();
    };

    prefetchC4(0, 0);
    prefetchC4(1, 1);

#pragma unroll
    for (int c4 = 0; c4 < 4; ++c4) {
      if (c4 == 3) { CP_WAIT(0); } else { CP_WAIT(1); }
      __syncthreads();
      if (c4 + 2 < 4) prefetchC4(c4 + 2, (c4 + 2) % 3);

      const uint32_t bs  = bsb + (uint32_t)(c4 % 3)*32768u;
      const uint32_t aBh = pA + (uint32_t)c4*128u;
      const uint32_t aBl = pA + (uint32_t)(4 + c4)*128u;
#pragma unroll
      for (int ks = 0; ks < 4; ++ks) {
        const int cc = ks*2 + jj;
        const uint32_t csw = (uint32_t)((cc ^ swA)*16);
        uint32_t ah[2][4], al[2][4];
        ldsm4(ah[0][0], ah[0][1], ah[0][2], ah[0][3], aBh + csw);
        ldsm4(ah[1][0], ah[1][1], ah[1][2], ah[1][3], aBh + 16384u + csw);
        ldsm4(al[0][0], al[0][1], al[0][2], al[0][3], aBl + csw);
        ldsm4(al[1][0], al[1][1], al[1][2], al[1][3], aBl + 16384u + csw);
        const uint32_t bsw = (uint32_t)((cc ^ swB)*16);
        uint32_t bh[2][4], bl[2][4];
#pragma unroll
        for (int qt = 0; qt < 2; ++qt) {
          ldsm4(bh[qt][0], bh[qt][1], bh[qt][2], bh[qt][3],
                bs + (uint32_t)nB*128u + (uint32_t)qt*2048u + bsw);
          ldsm4(bl[qt][0], bl[qt][1], bl[qt][2], bl[qt][3],
                bs + 16384u + (uint32_t)nB*128u + (uint32_t)qt*2048u + bsw);
        }
#pragma unroll
        for (int qt = 0; qt < 2; ++qt)
#pragma unroll
          for (int mt = 0; mt < 2; ++mt) {
            mma16816(acc[mt][qt*2  ][0], acc[mt][qt*2  ][1], acc[mt][qt*2  ][2], acc[mt][qt*2  ][3],
                     ah[mt][0], ah[mt][1], ah[mt][2], ah[mt][3], bh[qt][0], bh[qt][2]);
            mma16816(acc[mt][qt*2+1][0], acc[mt][qt*2+1][1], acc[mt][qt*2+1][2], acc[mt][qt*2+1][3],
                     ah[mt][0], ah[mt][1], ah[mt][2], ah[mt][3], bh[qt][1], bh[qt][3]);
          }
#pragma unroll
        for (int qt = 0; qt < 2; ++qt)
#pragma unroll
          for (int mt = 0; mt < 2; ++mt) {
            mma16816(acc[mt][qt*2  ][0], acc[mt][qt*2  ][1], acc[mt][qt*2  ][2], acc[mt][qt*2  ][3],
                     al[mt][0], al[mt][1], al[mt][2], al[mt][3], bh[qt][0], bh[qt][2]);
            mma16816(acc[mt][qt*2+1][0], acc[mt][qt*2+1][1], acc[mt][qt*2+1][2], acc[mt][qt*2+1][3],
                     al[mt][0], al[mt][1], al[mt][2], al[mt][3], bh[qt][1], bh[qt][3]);
          }
#pragma unroll
        for (int qt = 0; qt < 2; ++qt)
#pragma unroll
          for (int mt = 0; mt < 2; ++mt) {
            mma16816(acc[mt][qt*2  ][0], acc[mt][qt*2  ][1], acc[mt][qt*2  ][2], acc[mt][qt*2  ][3],
                     ah[mt][0], ah[mt][1], ah[mt][2], ah[mt][3], bl[qt][0], bl[qt][2]);
            mma16816(acc[mt][qt*2+1][0], acc[mt][qt*2+1][1], acc[mt][qt*2+1][2], acc[mt][qt*2+1][3],
                     ah[mt][0], ah[mt][1], ah[mt][2], ah[mt][3], bl[qt][1], bl[qt][3]);
          }
      }
    }
    __syncthreads();   // protect buf0 from next nt's prefetch

    // ---- epilogue ----
    if (MODE == 0 || MODE == 2) {
#pragma unroll
      for (int mt = 0; mt < 2; ++mt)
#pragma unroll
        for (int h = 0; h < 2; ++h) {
          int row = r0 + mw*32 + mt*16 + (lane >> 2) + h*8;
#pragma unroll
          for (int j = 0; j < 4; ++j) {
            int col = nt*128 + nw*32 + j*8 + (lane & 3)*2;
            float ox = acc[mt][j][h*2+0] + c0[col];
            float oy = acc[mt][j][h*2+1] + c0[col+1];
            if (MODE == 0) {
              float2 o; o.x = ox; o.y = oy;
              *reinterpret_cast<float2*>((float*)OutV + (size_t)row*256 + col) = o;
            } else {
              __half2 o = __floats2half2_rn(ox, oy);
              *reinterpret_cast<__half2*>((__half*)OutV + (size_t)row*256 + col) = o;
            }
          }
        }
    } else {
      const float2* sw2 = reinterpret_cast<const float2*>(c0);
      float* Out = (float*)OutV;
      int g = (N0 + nt*128 + nw*32) >> 5;
      float wx[4][2], wy[4][2], wl[4][2];
#pragma unroll
      for (int j = 0; j < 4; ++j) {
        int col = g*32 + j*8 + (lane & 3)*2;
        float2 q0 = __ldg(&sw2[col]), q1 = __ldg(&sw2[col+1]);
        wx[j][0] = q0.x; wy[j][0] = q0.y;
        wx[j][1] = q1.x; wy[j][1] = q1.y;
        wl[j][0] = __ldg(&c1[col]); wl[j][1] = __ldg(&c1[col+1]);
      }
#pragma unroll
      for (int mt = 0; mt < 2; ++mt)
#pragma unroll
        for (int h = 0; h < 2; ++h) {
          int row = r0 + mw*32 + mt*16 + (lane >> 2) + h*8;
          float sx = 0.f, sy = 0.f, sl = 0.f;
#pragma unroll
          for (int j = 0; j < 4; ++j) {
            float v0 = acc[mt][j][h*2+0];
            float v1 = acc[mt][j][h*2+1];
            v0 = v0 / (1.f + __expf(-v0));
            v1 = v1 / (1.f + __expf(-v1));
            sx = fmaf(v0, wx[j][0], sx); sx = fmaf(v1, wx[j][1], sx);
            sy = fmaf(v0, wy[j][0], sy); sy = fmaf(v1, wy[j][1], sy);
            sl = fmaf(v0, wl[j][0], sl); sl = fmaf(v1, wl[j][1], sl);
          }
          sx += __shfl_xor_sync(0xffffffffu, sx, 1);
          sy += __shfl_xor_sync(0xffffffffu, sy, 1);
          sl += __shfl_xor_sync(0xffffffffu, sl, 1);
          sx += __shfl_xor_sync(0xffffffffu, sx, 2);
          sy += __shfl_xor_sync(0xffffffffu, sy, 2);
          sl += __shfl_xor_sync(0xffffffffu, sl, 2);
          if ((lane & 3) == 0) {
            float* o = Out + ((size_t)g*MTOT + row)*3;
            o[0] = sx; o[1] = sy; o[2] = sl;
          }
        }
    }
  }
}

// mega: y<16 -> offset GEMM (NT=2, N0=y*256); y==16 -> value proj (NT=2, N=256)
__global__ void __launch_bounds__(512, 1)
mega_gemm(const uint4* __restrict__ Qh, const uint4* __restrict__ Ql,
          const uint4* __restrict__ Wh, const uint4* __restrict__ Wl,
          const float* __restrict__ sow, const float* __restrict__ attw,
          float* __restrict__ pofa,
          const uint4* __restrict__ Ih, const uint4* __restrict__ Il,
          const uint4* __restrict__ Vh, const uint4* __restrict__ Vl,
          const float* __restrict__ vbias, __half* __restrict__ pval) {
  const int r0 = blockIdx.x * 128;
  if (blockIdx.y < 16)
    gemm_body<1,2>(Qh, Ql, Wh, Wl, sow, attw, pofa, r0, blockIdx.y*256);
  else
    gemm_body<2,2>(Ih, Il, Vh, Vl, vbias, nullptr, pval, r0, 0);
}

template<int MODE, int NT>
__global__ void __launch_bounds__(512, 1)
gemm_mma(const uint4* __restrict__ Ah, const uint4* __restrict__ Al,
         const uint4* __restrict__ Bh, const uint4* __restrict__ Bl,
         const float* __restrict__ c0, const float* __restrict__ c1,
         void* __restrict__ OutV) {
  gemm_body<MODE,NT>(Ah, Al, Bh, Bl, c0, c1, OutV,
                     blockIdx.x*128, blockIdx.y*NT*128);
}

// ===========================================================================
// Sampling: one warp per (b,q,head); 2 points per warp via half2 lanes.
// ===========================================================================
__global__ void __launch_bounds__(256)
sample_kernel(const float* __restrict__ ref, const float* __restrict__ sob,
              const float* __restrict__ attb) {
  __shared__ float s_lx[NH][16], s_ly[NH][16], s_aw[NH][16];
  const int bq   = blockIdx.x;
  const int b    = bq / LEN;
  const int h    = threadIdx.x >> 5;
  const int lane = threadIdx.x & 31;
  const int p    = lane & 15;
  const int l    = p >> 2;

  const float SZ[4] = {64.f, 32.f, 16.f, 8.f};
  int g = h*16 + p;
  size_t ob = ((size_t)g*MTOT + bq)*3;
  float rx = g_offaw[ob+0], ry = g_offaw[ob+1], rl = g_offaw[ob+2];
  float inv = 1.f / SZ[l];
  float lx = ref[(size_t)bq*8 + l*2 + 0] + (rx + sob[g*2+0]) * inv;
  float ly = ref[(size_t)bq*8 + l*2 + 1] + (ry + sob[g*2+1]) * inv;
  float logit = rl + attb[g];

  float mx = logit;
#pragma unroll
  for (int off = 8; off; off >>= 1)
    mx = fmaxf(mx, __shfl_xor_sync(0xffffffffu, mx, off, 16));
  float e = __expf(logit - mx);
  float ssum = e;
#pragma unroll
  for (int off = 8; off; off >>= 1)
    ssum += __shfl_xor_sync(0xffffffffu, ssum, off, 16);
  float aw = e / ssum;

  if (lane < 16) { s_lx[h][p] = lx; s_ly[h][p] = ly; s_aw[h][p] = aw; }
  __syncwarp(0xffffffffu);

  const int ST[4]  = {0, 4096, 5120, 5376};
  const int SZI[4] = {64, 32, 16, 8};
  const int halfid = lane >> 4;        // 0: even points, 1: odd points
  const int dpair  = lane & 15;        // dim-pair index (dims 2d, 2d+1)
  float ax = 0.f, ay = 0.f;
  const __half2* vb2 = reinterpret_cast<const __half2*>(g_value)
                     + (size_t)b*LEN*128 + h*16 + dpair;

#pragma unroll
  for (int t = 0; t < 8; ++t) {
    int pp = t*2 + halfid;
    int ll = pp >> 2;
    int S  = SZI[ll];
    float x = s_lx[h][pp]*(float)S - 0.5f;
    float y = s_ly[h][pp]*(float)S - 0.5f;
    float w = s_aw[h][pp];
    float fx = floorf(x), fy = floorf(y);
    int x0 = (int)fx, y0 = (int)fy;
    float wx = x - fx, wy = y - fy;
    const __half2* vl = vb2 + (size_t)ST[ll]*128;
    __half2 z = __floats2half2_rn(0.f, 0.f);
    __half2 v00 = z, v01 = z, v10 = z, v11 = z;
    bool xa = (x0   >= 0) && (x0   < S);
    bool xb = (x0+1 >= 0) && (x0+1 < S);
    bool ya = (y0   >= 0) && (y0   < S);
    bool yb = (y0+1 >= 0) && (y0+1 < S);
    if (xa && ya) v00 = vl[(size_t)(y0*S + x0  )*128];
    if (xb && ya) v01 = vl[(size_t)(y0*S + x0+1)*128];
    if (xa && yb) v10 = vl[(size_t)((y0+1)*S + x0  )*128];
    if (xb && yb) v11 = vl[(size_t)((y0+1)*S + x0+1)*128];
    float2 f00 = __half22float2(v00), f01 = __half22float2(v01);
    float2 f10 = __half22float2(v10), f11 = __half22float2(v11);
    float w00 = (1.f-wx)*(1.f-wy)*w, w01 = wx*(1.f-wy)*w;
    float w10 = (1.f-wx)*wy*w,       w11 = wx*wy*w;
    ax += f00.x*w00 + f01.x*w01 + f10.x*w10 + f11.x*w11;
    ay += f00.y*w00 + f01.y*w01 + f10.y*w10 + f11.y*w11;
  }
  // combine even-point and odd-point halves
  ax += __shfl_xor_sync(0xffffffffu, ax, 16);
  ay += __shfl_xor_sync(0xffffffffu, ay, 16);

  if (lane < 16) {
    __nv_bfloat16 hx = __float2bfloat16_rn(ax);
    __nv_bfloat16 hy = __float2bfloat16_rn(ay);
    __nv_bfloat162 hi2(hx, hy);
    __nv_bfloat162 lo2(__float2bfloat16_rn(ax - __bfloat162float(hx)),
                       __float2bfloat16_rn(ay - __bfloat162float(hy)));
    size_t idx = (size_t)bq*128 + h*16 + dpair;
    reinterpret_cast<__nv_bfloat162*>(g_mh)[idx] = hi2;
    reinterpret_cast<__nv_bfloat162*>(g_ml)[idx] = lo2;
  }
}

// ===========================================================================
extern "C" void kernel_launch(void* const* d_in, const int* in_sizes, int n_in,
                              void* d_out, int out_size) {
  (void)in_sizes; (void)n_in; (void)out_size;
  const float* query  = (const float*)d_in[0];
  const float* ref    = (const float*)d_in[1];
  const float* inputf = (const float*)d_in[2];
  const float* oeW    = (const float*)d_in[4];
  const float* sow    = (const float*)d_in[5];
  const float* sob    = (const float*)d_in[6];
  const float* attW   = (const float*)d_in[7];
  const float* attb   = (const float*)d_in[8];
  const float* valW   = (const float*)d_in[9];
  const float* valb   = (const float*)d_in[10];
  const float* outW   = (const float*)d_in[11];
  const float* outb   = (const float*)d_in[12];
  float* out = (float*)d_out;

  uint4 *qh,*ql,*ifh,*ifl,*mh,*ml,*wembh,*wembl,*vwh,*vwl,*owh,*owl;
  void *pval; float *pofa;
  cudaGetSymbolAddress((void**)&qh, g_qh);     cudaGetSymbolAddress((void**)&ql, g_ql);
  cudaGetSymbolAddress((void**)&ifh, g_ifh);   cudaGetSymbolAddress((void**)&ifl, g_ifl);
  cudaGetSymbolAddress((void**)&mh, g_mh);     cudaGetSymbolAddress((void**)&ml, g_ml);
  cudaGetSymbolAddress((void**)&wembh, g_wembh); cudaGetSymbolAddress((void**)&wembl, g_wembl);
  cudaGetSymbolAddress((void**)&vwh, g_vwh);   cudaGetSymbolAddress((void**)&vwl, g_vwl);
  cudaGetSymbolAddress((void**)&owh, g_owh);   cudaGetSymbolAddress((void**)&owl, g_owl);
  cudaGetSymbolAddress((void**)&pval, g_value);
  cudaGetSymbolAddress((void**)&pofa, g_offaw);

  const int dynsmem = 131072 + 3*32768;  // 224 KB
  cudaFuncSetAttribute(mega_gemm, cudaFuncAttributeMaxDynamicSharedMemorySize, dynsmem);
  cudaFuncSetAttribute(gemm_mma<0,2>, cudaFuncAttributeMaxDynamicSharedMemorySize, dynsmem);

  const int n4 = MTOT*64;
  split_rm<<<n4/256, 256>>>(reinterpret_cast<const float4*>(query),
                            reinterpret_cast<__nv_bfloat162*>(qh),
                            reinterpret_cast<__nv_bfloat162*>(ql), n4);       // 0
  split_rm<<<1024, 256>>>(reinterpret_cast<const float4*>(oeW),
                          reinterpret_cast<__nv_bfloat162*>(wembh),
                          reinterpret_cast<__nv_bfloat162*>(wembl), 4096*64); // 1
  split_ifw<<<5568, 256>>>(reinterpret_cast<const float4*>(inputf),
                           reinterpret_cast<__nv_bfloat162*>(ifh),
                           reinterpret_cast<__nv_bfloat162*>(ifl),
                           reinterpret_cast<const float4*>(valW),
                           reinterpret_cast<__nv_bfloat162*>(vwh),
                           reinterpret_cast<__nv_bfloat162*>(vwl),
                           reinterpret_cast<const float4*>(outW),
                           reinterpret_cast<__nv_bfloat162*>(owh),
                           reinterpret_cast<__nv_bfloat162*>(owl));           // 2
  mega_gemm<<<dim3(MTOT/128,17), 512, dynsmem>>>(qh, ql, wembh, wembl,
                                                 sow, attW, pofa,
                                                 ifh, ifl, vwh, vwl,
                                                 valb, (__half*)pval);        // 3
  sample_kernel<<<MTOT, 256>>>(ref, sob, attb);                               // 4
  gemm_mma<0,2><<<dim3(MTOT/128,1), 512, dynsmem>>>(mh, ml, owh, owl,
                                                    outb, nullptr, out);      // 5
}